// round 5
// baseline (speedup 1.0000x reference)
#include <cuda_runtime.h>
#include <math.h>
#include <stdint.h>

#define DIM   768
#define HEADS 16
#define DK    48
#define B     2
#define S     2048
#define MROWS (B * S)          // 4096

// Scratch (static device globals — no runtime allocation)
// g_q/g_k/g_v hold tf32 bit patterns (pre-converted in GEMM epilogue).
__device__ float g_q[B * HEADS * S * DK];
__device__ float g_k[B * HEADS * S * DK];
__device__ float g_v[B * HEADS * S * DK];
__device__ float g_ctx[MROWS * DIM];

// ---------------------------------------------------------------------------
// tf32 helpers
// ---------------------------------------------------------------------------
__device__ __forceinline__ uint32_t f2tf32(float f) {
    uint32_t r;
    asm("cvt.rna.tf32.f32 %0, %1;" : "=r"(r) : "f"(f));
    return r;
}

__device__ __forceinline__ void mma_tf32(float c[4],
                                         const uint32_t a[4],
                                         const uint32_t b[2]) {
    asm volatile(
        "mma.sync.aligned.m16n8k8.row.col.f32.tf32.tf32.f32 "
        "{%0,%1,%2,%3}, {%4,%5,%6,%7}, {%8,%9}, {%0,%1,%2,%3};\n"
        : "+f"(c[0]), "+f"(c[1]), "+f"(c[2]), "+f"(c[3])
        : "r"(a[0]), "r"(a[1]), "r"(a[2]), "r"(a[3]),
          "r"(b[0]), "r"(b[1]));
}

// ---------------------------------------------------------------------------
// Tensor-core GEMM: out = A[M,K] @ W[N,K]^T + bias[N]   (tf32 in, fp32 accum)
// Block tile 128x64, BK=32, 256 threads = 8 warps as 4x2 (warp tile 32x32).
// Pair-interleaved smem layout: element (row, c) at
//   row*AP + (c/8)*8 + (c%4)*2 + (c%8)/4
// so each mma fragment pair (c, c+4) is one LDS.64. Pitch AP=40 (== 8 mod 32)
// keeps LDS.64 phases conflict-free. Single __syncthreads per K-slab.
// MODE 0: plain fp32 out [M,N].
// MODE 1: scatter to [B,HEADS,S,DK], value = tf32_bits((acc+bias)*oscale).
// ---------------------------------------------------------------------------
#define BK 32
#define AP 40
#define A_WORDS (128 * AP)
#define B_WORDS (64 * AP)
#define SMEM_WORDS (2 * (A_WORDS + B_WORDS))

template <int MODE>
__global__ __launch_bounds__(256)
void gemm_tc_kernel(const float* __restrict__ A,
                    const float* __restrict__ W,
                    const float* __restrict__ bias,
                    float* __restrict__ out,
                    int M, int N, int K, float oscale)
{
    extern __shared__ uint32_t smem[];
    uint32_t* As = smem;                     // [2][128][AP]
    uint32_t* Bs = smem + 2 * A_WORDS;       // [2][64][AP]

    const int tid  = threadIdx.x;
    const int lane = tid & 31;
    const int warp = tid >> 5;
    const int warpM = warp >> 1;
    const int warpN = warp & 1;
    const int g   = lane >> 2;
    const int tig = lane & 3;

    const int bm = blockIdx.y * 128;
    const int bn = blockIdx.x * 64;

    const int lrA = tid >> 1;                // 0..127
    const int lkA = (tid & 1) * 16;          // 0 / 16
    const int lrB = tid >> 2;                // 0..63
    const int lkB = (tid & 3) * 8;           // 0/8/16/24

    const float* Aptr = A + (size_t)(bm + lrA) * K + lkA;
    const float* Wptr = W + (size_t)(bn + lrB) * K + lkB;

    float c[2][4][4];
    #pragma unroll
    for (int mt = 0; mt < 2; mt++)
        #pragma unroll
        for (int nt = 0; nt < 4; nt++)
            #pragma unroll
            for (int i = 0; i < 4; i++) c[mt][nt][i] = 0.0f;

    // interleaved store helper offsets: float4 at col c0 (c0 % 4 == 0)
    //   base = row*AP + (c0/8)*8 + (c0%8)/4 ; words at base + {0,2,4,6}
    // ---- prologue: stage slab 0 into buffer 0 ----
    {
        #pragma unroll
        for (int i = 0; i < 4; i++) {
            float4 v = *(const float4*)(Aptr + i * 4);
            const int c0 = lkA + i * 4;
            uint32_t* dst = &As[lrA * AP + (c0 >> 3) * 8 + ((c0 & 7) >> 2)];
            dst[0] = f2tf32(v.x); dst[2] = f2tf32(v.y);
            dst[4] = f2tf32(v.z); dst[6] = f2tf32(v.w);
        }
        #pragma unroll
        for (int i = 0; i < 2; i++) {
            float4 v = *(const float4*)(Wptr + i * 4);
            const int c0 = lkB + i * 4;
            uint32_t* dst = &Bs[lrB * AP + (c0 >> 3) * 8 + ((c0 & 7) >> 2)];
            dst[0] = f2tf32(v.x); dst[2] = f2tf32(v.y);
            dst[4] = f2tf32(v.z); dst[6] = f2tf32(v.w);
        }
    }
    __syncthreads();

    int buf = 0;
    const int arow = warpM * 32;
    const int bcol = warpN * 32;

    for (int k0 = 0; k0 < K; k0 += BK) {
        const bool more = (k0 + BK < K);
        float4 pa[4], pw[2];
        if (more) {
            #pragma unroll
            for (int i = 0; i < 4; i++) pa[i] = *(const float4*)(Aptr + k0 + BK + i * 4);
            #pragma unroll
            for (int i = 0; i < 2; i++) pw[i] = *(const float4*)(Wptr + k0 + BK + i * 4);
        }

        const uint32_t* Ab = As + buf * A_WORDS;
        const uint32_t* Bb = Bs + buf * B_WORDS;
        #pragma unroll
        for (int ks = 0; ks < 4; ks++) {
            const int kc = ks * 8;
            uint32_t afr[2][4], bfr[4][2];
            #pragma unroll
            for (int mt = 0; mt < 2; mt++) {
                const int r0w = arow + mt * 16;
                uint2 u0 = *(const uint2*)&Ab[(r0w + g)     * AP + kc + tig * 2];
                uint2 u1 = *(const uint2*)&Ab[(r0w + g + 8) * AP + kc + tig * 2];
                afr[mt][0] = u0.x; afr[mt][1] = u1.x;
                afr[mt][2] = u0.y; afr[mt][3] = u1.y;
            }
            #pragma unroll
            for (int nt = 0; nt < 4; nt++) {
                uint2 ub = *(const uint2*)&Bb[(bcol + nt * 8 + g) * AP + kc + tig * 2];
                bfr[nt][0] = ub.x; bfr[nt][1] = ub.y;
            }
            #pragma unroll
            for (int mt = 0; mt < 2; mt++)
                #pragma unroll
                for (int nt = 0; nt < 4; nt++)
                    mma_tf32(c[mt][nt], afr[mt], bfr[nt]);
        }

        if (more) {
            uint32_t* Aw = As + (buf ^ 1) * A_WORDS;
            uint32_t* Bw = Bs + (buf ^ 1) * B_WORDS;
            #pragma unroll
            for (int i = 0; i < 4; i++) {
                const int c0 = lkA + i * 4;
                uint32_t* dst = &Aw[lrA * AP + (c0 >> 3) * 8 + ((c0 & 7) >> 2)];
                dst[0] = f2tf32(pa[i].x); dst[2] = f2tf32(pa[i].y);
                dst[4] = f2tf32(pa[i].z); dst[6] = f2tf32(pa[i].w);
            }
            #pragma unroll
            for (int i = 0; i < 2; i++) {
                const int c0 = lkB + i * 4;
                uint32_t* dst = &Bw[lrB * AP + (c0 >> 3) * 8 + ((c0 & 7) >> 2)];
                dst[0] = f2tf32(pw[i].x); dst[2] = f2tf32(pw[i].y);
                dst[4] = f2tf32(pw[i].z); dst[6] = f2tf32(pw[i].w);
            }
            __syncthreads();
            buf ^= 1;
        }
    }

    // ---- epilogue ----
    #pragma unroll
    for (int mt = 0; mt < 2; mt++) {
        #pragma unroll
        for (int nt = 0; nt < 4; nt++) {
            #pragma unroll
            for (int i = 0; i < 4; i++) {
                const int m = bm + arow + mt * 16 + g + (i >> 1) * 8;
                const int n = bn + bcol + nt * 8 + 2 * tig + (i & 1);
                const float v = c[mt][nt][i] + bias[n];
                if (MODE == 0) {
                    out[(size_t)m * N + n] = v;
                } else {
                    const int bidx = m / S;
                    const int s    = m % S;
                    const int h    = n / DK;
                    const int d    = n % DK;
                    out[(((size_t)bidx * HEADS + h) * S + s) * DK + d] =
                        __uint_as_float(f2tf32(v * oscale));
                }
            }
        }
    }
}

// ---------------------------------------------------------------------------
// Tensor-core flash attention (tf32 mma), pair-interleaved K/V smem layouts.
// Q/K/V arrive pre-converted to tf32 bits (Q pre-scaled by 1/sqrt(dk)).
// K layout:  (row, c) -> row*KP + (c/8)*8 + (c%4)*2 + (c%8)/4        KP=56
// V layout:  (r, c)   -> ((r/8)*4 + r%4)*VP + c*2 + (r%8)/4          VP=104
// -> every mma B-fragment is one conflict-free LDS.64.
// ---------------------------------------------------------------------------
#define KP 56
#define VP 104
#define PPITCH 68
#define ATT_SMEM_WORDS (64 * KP + 32 * VP + 128 * PPITCH)

__global__ __launch_bounds__(256)
void attention_mma_kernel(const float* __restrict__ Q,
                          const float* __restrict__ K,
                          const float* __restrict__ V,
                          float* __restrict__ ctx)
{
    extern __shared__ uint32_t sm[];
    uint32_t* Ks = sm;                              // [64][KP]
    uint32_t* Vs = sm + 64 * KP;                    // [32][VP]  (row pairs)
    uint32_t* Ps = sm + 64 * KP + 32 * VP;          // [128][PPITCH]

    const int qt   = blockIdx.x;
    const int h    = blockIdx.y;
    const int b    = blockIdx.z;
    const int tid  = threadIdx.x;
    const int lane = tid & 31;
    const int warp = tid >> 5;
    const int g    = lane >> 2;
    const int tig  = lane & 3;
    const int r0   = warp * 16;

    const size_t head_off = ((size_t)b * HEADS + h) * S * DK;

    // ---- stage Q tile (already tf32 + scaled): plain copy ----
    {
        const uint4* qsrc = (const uint4*)(Q + head_off + (size_t)qt * 128 * DK);
        #pragma unroll
        for (int i = tid; i < 128 * 12; i += 256) {
            const int row = i / 12, c4 = (i % 12) * 4;
            *(uint4*)&Ps[row * PPITCH + c4] = qsrc[i];
        }
    }
    __syncthreads();

    // ---- Q fragments -> registers (reused for all KV iterations) ----
    uint32_t qf[6][4];
    #pragma unroll
    for (int ks = 0; ks < 6; ks++) {
        const int kc = ks * 8;
        qf[ks][0] = Ps[(r0 + g)     * PPITCH + kc + tig];
        qf[ks][1] = Ps[(r0 + g + 8) * PPITCH + kc + tig];
        qf[ks][2] = Ps[(r0 + g)     * PPITCH + kc + tig + 4];
        qf[ks][3] = Ps[(r0 + g + 8) * PPITCH + kc + tig + 4];
    }

    float ctxa[6][4];
    #pragma unroll
    for (int nt = 0; nt < 6; nt++)
        #pragma unroll
        for (int i = 0; i < 4; i++) ctxa[nt][i] = 0.0f;
    float mrun0 = -INFINITY, mrun1 = -INFINITY;
    float lrun0 = 0.0f,      lrun1 = 0.0f;

    const uint4* kb = (const uint4*)(K + head_off);
    const uint4* vb = (const uint4*)(V + head_off);

    for (int kt = 0; kt < S / 64; kt++) {
        __syncthreads();

        // ---- stage K and V tiles (pre-converted; permuted copies) ----
        {
            const uint4* ksrc = kb + (size_t)kt * 64 * 12;
            const uint4* vsrc = vb + (size_t)kt * 64 * 12;
            #pragma unroll
            for (int i = tid; i < 768; i += 256) {
                const int row = i / 12, c0 = (i % 12) * 4;
                uint4 kv = ksrc[i];
                uint32_t* kd = &Ks[row * KP + ((c0 >> 3) << 3) + ((c0 & 7) >> 2)];
                kd[0] = kv.x; kd[2] = kv.y; kd[4] = kv.z; kd[6] = kv.w;
                uint4 vv = vsrc[i];
                const int pr = (row >> 3) * 4 + (row & 3);
                const int j  = (row & 7) >> 2;
                uint32_t* vd = &Vs[pr * VP + c0 * 2 + j];
                vd[0] = vv.x; vd[2] = vv.y; vd[4] = vv.z; vd[6] = vv.w;
            }
        }
        __syncthreads();

        // ---- scores = Q @ K^T on tensor pipe ----
        float sc[8][4];
        #pragma unroll
        for (int nt = 0; nt < 8; nt++)
            #pragma unroll
            for (int i = 0; i < 4; i++) sc[nt][i] = 0.0f;

        #pragma unroll
        for (int ks = 0; ks < 6; ks++) {
            const int kc = ks * 8;
            #pragma unroll
            for (int nt = 0; nt < 8; nt++) {
                uint2 ub = *(const uint2*)&Ks[(nt * 8 + g) * KP + kc + tig * 2];
                uint32_t bfr[2] = { ub.x, ub.y };
                mma_tf32(sc[nt], qf[ks], bfr);
            }
        }

        // ---- online softmax (register + shfl; rows warp-local) ----
        float m0 = sc[0][0], m1 = sc[0][2];
        #pragma unroll
        for (int nt = 0; nt < 8; nt++) {
            m0 = fmaxf(m0, fmaxf(sc[nt][0], sc[nt][1]));
            m1 = fmaxf(m1, fmaxf(sc[nt][2], sc[nt][3]));
        }
        m0 = fmaxf(m0, __shfl_xor_sync(0xFFFFFFFF, m0, 1));
        m0 = fmaxf(m0, __shfl_xor_sync(0xFFFFFFFF, m0, 2));
        m1 = fmaxf(m1, __shfl_xor_sync(0xFFFFFFFF, m1, 1));
        m1 = fmaxf(m1, __shfl_xor_sync(0xFFFFFFFF, m1, 2));

        const float mn0 = fmaxf(mrun0, m0);
        const float mn1 = fmaxf(mrun1, m1);
        const float corr0 = __expf(mrun0 - mn0);
        const float corr1 = __expf(mrun1 - mn1);
        mrun0 = mn0; mrun1 = mn1;
        lrun0 *= corr0; lrun1 *= corr1;
        #pragma unroll
        for (int nt = 0; nt < 6; nt++) {
            ctxa[nt][0] *= corr0; ctxa[nt][1] *= corr0;
            ctxa[nt][2] *= corr1; ctxa[nt][3] *= corr1;
        }

        #pragma unroll
        for (int nt = 0; nt < 8; nt++) {
            float p0 = __expf(sc[nt][0] - mn0);
            float p1 = __expf(sc[nt][1] - mn0);
            float p2 = __expf(sc[nt][2] - mn1);
            float p3 = __expf(sc[nt][3] - mn1);
            lrun0 += p0 + p1;
            lrun1 += p2 + p3;
            uint2 u01 = { f2tf32(p0), f2tf32(p1) };
            uint2 u23 = { f2tf32(p2), f2tf32(p3) };
            *(uint2*)&Ps[(r0 + g)     * PPITCH + nt * 8 + 2 * tig] = u01;
            *(uint2*)&Ps[(r0 + g + 8) * PPITCH + nt * 8 + 2 * tig] = u23;
        }
        __syncwarp();

        // ---- ctx += P @ V on tensor pipe ----
        #pragma unroll
        for (int ks = 0; ks < 8; ks++) {
            const int kc = ks * 8;
            uint32_t afr[4];
            afr[0] = Ps[(r0 + g)     * PPITCH + kc + tig];
            afr[1] = Ps[(r0 + g + 8) * PPITCH + kc + tig];
            afr[2] = Ps[(r0 + g)     * PPITCH + kc + tig + 4];
            afr[3] = Ps[(r0 + g + 8) * PPITCH + kc + tig + 4];
            #pragma unroll
            for (int nt = 0; nt < 6; nt++) {
                uint2 uv = *(const uint2*)&Vs[(ks * 4 + tig) * VP + (nt * 8 + g) * 2];
                uint32_t bfr[2] = { uv.x, uv.y };
                mma_tf32(ctxa[nt], afr, bfr);
            }
        }
    }

    // ---- epilogue ----
    lrun0 += __shfl_xor_sync(0xFFFFFFFF, lrun0, 1);
    lrun0 += __shfl_xor_sync(0xFFFFFFFF, lrun0, 2);
    lrun1 += __shfl_xor_sync(0xFFFFFFFF, lrun1, 1);
    lrun1 += __shfl_xor_sync(0xFFFFFFFF, lrun1, 2);
    const float inv0 = 1.0f / lrun0;
    const float inv1 = 1.0f / lrun1;

    const int srow0 = qt * 128 + r0 + g;
    float* out0 = ctx + ((size_t)b * S + srow0)     * DIM + h * DK;
    float* out1 = ctx + ((size_t)b * S + srow0 + 8) * DIM + h * DK;
    #pragma unroll
    for (int nt = 0; nt < 6; nt++) {
        const int col = nt * 8 + 2 * tig;
        float2 o0 = { ctxa[nt][0] * inv0, ctxa[nt][1] * inv0 };
        float2 o1 = { ctxa[nt][2] * inv1, ctxa[nt][3] * inv1 };
        *(float2*)(out0 + col) = o0;
        *(float2*)(out1 + col) = o1;
    }
}

// ---------------------------------------------------------------------------
extern "C" void kernel_launch(void* const* d_in, const int* in_sizes, int n_in,
                              void* d_out, int out_size)
{
    const float* x  = (const float*)d_in[0];
    const float* Wq = (const float*)d_in[1];
    const float* bq = (const float*)d_in[2];
    const float* Wk = (const float*)d_in[3];
    const float* bk = (const float*)d_in[4];
    const float* Wv = (const float*)d_in[5];
    const float* bv = (const float*)d_in[6];
    const float* Wo = (const float*)d_in[7];
    const float* bo = (const float*)d_in[8];
    float* out = (float*)d_out;

    float *q, *k, *v, *ctx;
    cudaGetSymbolAddress((void**)&q,   g_q);
    cudaGetSymbolAddress((void**)&k,   g_k);
    cudaGetSymbolAddress((void**)&v,   g_v);
    cudaGetSymbolAddress((void**)&ctx, g_ctx);

    const int gemm_smem = SMEM_WORDS * 4;
    cudaFuncSetAttribute(gemm_tc_kernel<0>,
                         cudaFuncAttributeMaxDynamicSharedMemorySize, gemm_smem);
    cudaFuncSetAttribute(gemm_tc_kernel<1>,
                         cudaFuncAttributeMaxDynamicSharedMemorySize, gemm_smem);
    const int att_smem = ATT_SMEM_WORDS * 4;
    cudaFuncSetAttribute(attention_mma_kernel,
                         cudaFuncAttributeMaxDynamicSharedMemorySize, att_smem);

    const float qscale = 0.14433756729740643f;   // 1/sqrt(48)

    dim3 gblk(256);
    dim3 ggrd(DIM / 64, MROWS / 128);   // (12, 32)

    gemm_tc_kernel<1><<<ggrd, gblk, gemm_smem>>>(x, Wq, bq, q, MROWS, DIM, DIM, qscale);
    gemm_tc_kernel<1><<<ggrd, gblk, gemm_smem>>>(x, Wk, bk, k, MROWS, DIM, DIM, 1.0f);
    gemm_tc_kernel<1><<<ggrd, gblk, gemm_smem>>>(x, Wv, bv, v, MROWS, DIM, DIM, 1.0f);

    dim3 agrd(S / 128, HEADS, B);       // (16, 16, 2)
    attention_mma_kernel<<<agrd, 256, att_smem>>>(q, k, v, ctx);

    gemm_tc_kernel<0><<<ggrd, gblk, gemm_smem>>>(ctx, Wo, bo, out, MROWS, DIM, DIM, 1.0f);
}

// round 6
// speedup vs baseline: 1.4419x; 1.4419x over previous
#include <cuda_runtime.h>
#include <math.h>
#include <stdint.h>

#define DIM   768
#define HEADS 16
#define DK    48
#define B     2
#define S     2048
#define MROWS (B * S)          // 4096

// Scratch (static device globals — no runtime allocation)
// g_q/g_k/g_v hold tf32 bit patterns (pre-converted in GEMM epilogue;
// g_q additionally pre-scaled by 1/sqrt(dk)).
__device__ float g_q[B * HEADS * S * DK];
__device__ float g_k[B * HEADS * S * DK];
__device__ float g_v[B * HEADS * S * DK];
__device__ float g_ctx[MROWS * DIM];

// ---------------------------------------------------------------------------
// tf32 helpers
// ---------------------------------------------------------------------------
__device__ __forceinline__ uint32_t f2tf32(float f) {
    uint32_t r;
    asm("cvt.rna.tf32.f32 %0, %1;" : "=r"(r) : "f"(f));
    return r;
}

__device__ __forceinline__ void mma_tf32(float c[4],
                                         const uint32_t a[4],
                                         const uint32_t b[2]) {
    asm volatile(
        "mma.sync.aligned.m16n8k8.row.col.f32.tf32.tf32.f32 "
        "{%0,%1,%2,%3}, {%4,%5,%6,%7}, {%8,%9}, {%0,%1,%2,%3};\n"
        : "+f"(c[0]), "+f"(c[1]), "+f"(c[2]), "+f"(c[3])
        : "r"(a[0]), "r"(a[1]), "r"(a[2]), "r"(a[3]),
          "r"(b[0]), "r"(b[1]));
}

// ---------------------------------------------------------------------------
// Tensor-core GEMM (round-3 version, measured ~65us/GEMM):
// out = A[M,K] @ W[N,K]^T + bias[N]   (tf32 in, fp32 accum)
// Block tile 128x64, BK=32, 256 threads = 8 warps as 4x2 (warp tile 32x32).
// MODE 0: plain fp32 out [M,N].
// MODE 1: scatter to [B,HEADS,S,DK]; value stored as tf32 bits of
//         (acc + bias) * oscale  (pre-conversion for the attention kernel).
// ---------------------------------------------------------------------------
#define BK 32
#define APITCH 36
#define A_WORDS (128 * APITCH)
#define B_WORDS (64 * APITCH)
#define SMEM_WORDS (2 * (A_WORDS + B_WORDS))

template <int MODE>
__global__ __launch_bounds__(256)
void gemm_tc_kernel(const float* __restrict__ A,
                    const float* __restrict__ W,
                    const float* __restrict__ bias,
                    float* __restrict__ out,
                    int M, int N, int K, float oscale)
{
    extern __shared__ uint32_t smem[];
    uint32_t* As = smem;
    uint32_t* Bs = smem + 2 * A_WORDS;

    const int tid  = threadIdx.x;
    const int lane = tid & 31;
    const int warp = tid >> 5;
    const int warpM = warp >> 1;
    const int warpN = warp & 1;
    const int g   = lane >> 2;
    const int tig = lane & 3;

    const int bm = blockIdx.y * 128;
    const int bn = blockIdx.x * 64;

    const int lrA = tid >> 1;
    const int lkA = (tid & 1) * 16;
    const int lrB = tid >> 2;
    const int lkB = (tid & 3) * 8;

    const float* Aptr = A + (size_t)(bm + lrA) * K + lkA;
    const float* Wptr = W + (size_t)(bn + lrB) * K + lkB;

    float c[2][4][4];
    #pragma unroll
    for (int mt = 0; mt < 2; mt++)
        #pragma unroll
        for (int nt = 0; nt < 4; nt++)
            #pragma unroll
            for (int i = 0; i < 4; i++) c[mt][nt][i] = 0.0f;

    {
        #pragma unroll
        for (int i = 0; i < 4; i++) {
            float4 v = *(const float4*)(Aptr + i * 4);
            uint4 u = { f2tf32(v.x), f2tf32(v.y), f2tf32(v.z), f2tf32(v.w) };
            *(uint4*)&As[lrA * APITCH + lkA + i * 4] = u;
        }
        #pragma unroll
        for (int i = 0; i < 2; i++) {
            float4 v = *(const float4*)(Wptr + i * 4);
            uint4 u = { f2tf32(v.x), f2tf32(v.y), f2tf32(v.z), f2tf32(v.w) };
            *(uint4*)&Bs[lrB * APITCH + lkB + i * 4] = u;
        }
    }
    __syncthreads();

    int buf = 0;
    const int arow = warpM * 32;
    const int bcol = warpN * 32;

    for (int k0 = BK; k0 <= K; k0 += BK) {
        float4 pa[4], pw[2];
        const bool more = (k0 < K);
        if (more) {
            #pragma unroll
            for (int i = 0; i < 4; i++) pa[i] = *(const float4*)(Aptr + k0 + i * 4);
            #pragma unroll
            for (int i = 0; i < 2; i++) pw[i] = *(const float4*)(Wptr + k0 + i * 4);
        }

        const uint32_t* Ab = As + buf * A_WORDS;
        const uint32_t* Bb = Bs + buf * B_WORDS;
        #pragma unroll
        for (int ks = 0; ks < 4; ks++) {
            const int kc = ks * 8;
            uint32_t afr[2][4], bfr[4][2];
            #pragma unroll
            for (int mt = 0; mt < 2; mt++) {
                const int r0 = arow + mt * 16;
                afr[mt][0] = Ab[(r0 + g)     * APITCH + kc + tig];
                afr[mt][1] = Ab[(r0 + g + 8) * APITCH + kc + tig];
                afr[mt][2] = Ab[(r0 + g)     * APITCH + kc + tig + 4];
                afr[mt][3] = Ab[(r0 + g + 8) * APITCH + kc + tig + 4];
            }
            #pragma unroll
            for (int nt = 0; nt < 4; nt++) {
                const int n = bcol + nt * 8 + g;
                bfr[nt][0] = Bb[n * APITCH + kc + tig];
                bfr[nt][1] = Bb[n * APITCH + kc + tig + 4];
            }
            #pragma unroll
            for (int mt = 0; mt < 2; mt++)
                #pragma unroll
                for (int nt = 0; nt < 4; nt++)
                    mma_tf32(c[mt][nt], afr[mt], bfr[nt]);
        }

        if (more) {
            buf ^= 1;
            uint32_t* Aw = As + buf * A_WORDS;
            uint32_t* Bw = Bs + buf * B_WORDS;
            __syncthreads();
            #pragma unroll
            for (int i = 0; i < 4; i++) {
                uint4 u = { f2tf32(pa[i].x), f2tf32(pa[i].y), f2tf32(pa[i].z), f2tf32(pa[i].w) };
                *(uint4*)&Aw[lrA * APITCH + lkA + i * 4] = u;
            }
            #pragma unroll
            for (int i = 0; i < 2; i++) {
                uint4 u = { f2tf32(pw[i].x), f2tf32(pw[i].y), f2tf32(pw[i].z), f2tf32(pw[i].w) };
                *(uint4*)&Bw[lrB * APITCH + lkB + i * 4] = u;
            }
            __syncthreads();
        }
    }

    #pragma unroll
    for (int mt = 0; mt < 2; mt++) {
        #pragma unroll
        for (int nt = 0; nt < 4; nt++) {
            #pragma unroll
            for (int i = 0; i < 4; i++) {
                const int m = bm + arow + mt * 16 + g + (i >> 1) * 8;
                const int n = bn + bcol + nt * 8 + 2 * tig + (i & 1);
                const float v = c[mt][nt][i] + bias[n];
                if (MODE == 0) {
                    out[(size_t)m * N + n] = v;
                } else {
                    const int bidx = m / S;
                    const int s    = m % S;
                    const int h    = n / DK;
                    const int d    = n % DK;
                    out[(((size_t)bidx * HEADS + h) * S + s) * DK + d] =
                        __uint_as_float(f2tf32(v * oscale));
                }
            }
        }
    }
}

// ---------------------------------------------------------------------------
// Tensor-core flash attention (round-4 structure, measured 242us), with
// Q/K/V arriving pre-converted to tf32 bits -> staging is a pure uint4 copy
// (no cvt, STS.128 instead of 4x STS.32).
// ---------------------------------------------------------------------------
#define KPITCH 52
#define VPITCH 56
#define PPITCH 68
#define ATT_SMEM_WORDS (64 * KPITCH + 64 * VPITCH + 128 * PPITCH)

__global__ __launch_bounds__(256)
void attention_mma_kernel(const float* __restrict__ Q,
                          const float* __restrict__ K,
                          const float* __restrict__ V,
                          float* __restrict__ ctx)
{
    extern __shared__ uint32_t sm[];
    uint32_t* Ks = sm;                                   // [64][KPITCH]
    uint32_t* Vs = sm + 64 * KPITCH;                     // [64][VPITCH]
    uint32_t* Ps = sm + 64 * KPITCH + 64 * VPITCH;       // [128][PPITCH]

    const int qt   = blockIdx.x;
    const int h    = blockIdx.y;
    const int b    = blockIdx.z;
    const int tid  = threadIdx.x;
    const int lane = tid & 31;
    const int warp = tid >> 5;
    const int g    = lane >> 2;
    const int tig  = lane & 3;
    const int r0   = warp * 16;

    const size_t head_off = ((size_t)b * HEADS + h) * S * DK;

    // ---- stage Q tile (already tf32 + pre-scaled): pure copy ----
    {
        const uint4* qsrc = (const uint4*)(Q + head_off + (size_t)qt * 128 * DK);
        #pragma unroll
        for (int i = tid; i < 128 * 12; i += 256) {
            const int row = i / 12, c4 = (i % 12) * 4;
            *(uint4*)&Ps[row * PPITCH + c4] = qsrc[i];
        }
    }
    __syncthreads();

    // ---- Q fragments -> registers (reused all 32 KV iterations) ----
    uint32_t qf[6][4];
    #pragma unroll
    for (int ks = 0; ks < 6; ks++) {
        const int kc = ks * 8;
        qf[ks][0] = Ps[(r0 + g)     * PPITCH + kc + tig];
        qf[ks][1] = Ps[(r0 + g + 8) * PPITCH + kc + tig];
        qf[ks][2] = Ps[(r0 + g)     * PPITCH + kc + tig + 4];
        qf[ks][3] = Ps[(r0 + g + 8) * PPITCH + kc + tig + 4];
    }

    float ctxa[6][4];
    #pragma unroll
    for (int nt = 0; nt < 6; nt++)
        #pragma unroll
        for (int i = 0; i < 4; i++) ctxa[nt][i] = 0.0f;
    float mrun0 = -INFINITY, mrun1 = -INFINITY;
    float lrun0 = 0.0f,      lrun1 = 0.0f;

    const uint4* kb = (const uint4*)(K + head_off);
    const uint4* vb = (const uint4*)(V + head_off);

    for (int kt = 0; kt < S / 64; kt++) {
        __syncthreads();     // previous iteration done reading Ks/Vs

        // ---- stage K and V tiles: pure uint4 copies ----
        {
            const uint4* ksrc = kb + (size_t)kt * 64 * 12;
            const uint4* vsrc = vb + (size_t)kt * 64 * 12;
            #pragma unroll
            for (int i = tid; i < 768; i += 256) {
                const int row = i / 12, c4 = (i % 12) * 4;
                *(uint4*)&Ks[row * KPITCH + c4] = ksrc[i];
                *(uint4*)&Vs[row * VPITCH + c4] = vsrc[i];
            }
        }
        __syncthreads();

        // ---- scores = Q @ K^T on tensor pipe ----
        float sc[8][4];
        #pragma unroll
        for (int nt = 0; nt < 8; nt++)
            #pragma unroll
            for (int i = 0; i < 4; i++) sc[nt][i] = 0.0f;

        #pragma unroll
        for (int ks = 0; ks < 6; ks++) {
            const int kc = ks * 8;
            #pragma unroll
            for (int nt = 0; nt < 8; nt++) {
                uint32_t bfr[2];
                const uint32_t* kr = &Ks[(nt * 8 + g) * KPITCH + kc];
                bfr[0] = kr[tig];
                bfr[1] = kr[tig + 4];
                mma_tf32(sc[nt], qf[ks], bfr);
            }
        }

        // ---- online softmax (register + shfl; rows warp-local) ----
        float m0 = sc[0][0], m1 = sc[0][2];
        #pragma unroll
        for (int nt = 0; nt < 8; nt++) {
            m0 = fmaxf(m0, fmaxf(sc[nt][0], sc[nt][1]));
            m1 = fmaxf(m1, fmaxf(sc[nt][2], sc[nt][3]));
        }
        m0 = fmaxf(m0, __shfl_xor_sync(0xFFFFFFFF, m0, 1));
        m0 = fmaxf(m0, __shfl_xor_sync(0xFFFFFFFF, m0, 2));
        m1 = fmaxf(m1, __shfl_xor_sync(0xFFFFFFFF, m1, 1));
        m1 = fmaxf(m1, __shfl_xor_sync(0xFFFFFFFF, m1, 2));

        const float mn0 = fmaxf(mrun0, m0);
        const float mn1 = fmaxf(mrun1, m1);
        const float corr0 = __expf(mrun0 - mn0);   // exp(-inf)=0 first time
        const float corr1 = __expf(mrun1 - mn1);
        mrun0 = mn0; mrun1 = mn1;
        lrun0 *= corr0; lrun1 *= corr1;
        #pragma unroll
        for (int nt = 0; nt < 6; nt++) {
            ctxa[nt][0] *= corr0; ctxa[nt][1] *= corr0;
            ctxa[nt][2] *= corr1; ctxa[nt][3] *= corr1;
        }

        // exp + partial row-sums + store P (tf32) into warp-private slab
        #pragma unroll
        for (int nt = 0; nt < 8; nt++) {
            float p0 = __expf(sc[nt][0] - mn0);
            float p1 = __expf(sc[nt][1] - mn0);
            float p2 = __expf(sc[nt][2] - mn1);
            float p3 = __expf(sc[nt][3] - mn1);
            lrun0 += p0 + p1;
            lrun1 += p2 + p3;
            uint2 u01 = { f2tf32(p0), f2tf32(p1) };
            uint2 u23 = { f2tf32(p2), f2tf32(p3) };
            *(uint2*)&Ps[(r0 + g)     * PPITCH + nt * 8 + 2 * tig] = u01;
            *(uint2*)&Ps[(r0 + g + 8) * PPITCH + nt * 8 + 2 * tig] = u23;
        }
        __syncwarp();

        // ---- ctx += P @ V on tensor pipe ----
        #pragma unroll
        for (int ks = 0; ks < 8; ks++) {
            const int kc = ks * 8;
            uint32_t afr[4];
            afr[0] = Ps[(r0 + g)     * PPITCH + kc + tig];
            afr[1] = Ps[(r0 + g + 8) * PPITCH + kc + tig];
            afr[2] = Ps[(r0 + g)     * PPITCH + kc + tig + 4];
            afr[3] = Ps[(r0 + g + 8) * PPITCH + kc + tig + 4];
            #pragma unroll
            for (int nt = 0; nt < 6; nt++) {
                uint32_t bfr[2];
                const uint32_t* vr = &Vs[(kc + tig) * VPITCH + nt * 8 + g];
                bfr[0] = vr[0];
                bfr[1] = vr[4 * VPITCH];
                mma_tf32(ctxa[nt], afr, bfr);
            }
        }
    }

    // ---- epilogue: finish row sums, normalize, write ctx [B,S,DIM] ----
    lrun0 += __shfl_xor_sync(0xFFFFFFFF, lrun0, 1);
    lrun0 += __shfl_xor_sync(0xFFFFFFFF, lrun0, 2);
    lrun1 += __shfl_xor_sync(0xFFFFFFFF, lrun1, 1);
    lrun1 += __shfl_xor_sync(0xFFFFFFFF, lrun1, 2);
    const float inv0 = 1.0f / lrun0;
    const float inv1 = 1.0f / lrun1;

    const int srow0 = qt * 128 + r0 + g;
    float* out0 = ctx + ((size_t)b * S + srow0)     * DIM + h * DK;
    float* out1 = ctx + ((size_t)b * S + srow0 + 8) * DIM + h * DK;
    #pragma unroll
    for (int nt = 0; nt < 6; nt++) {
        const int col = nt * 8 + 2 * tig;
        float2 o0 = { ctxa[nt][0] * inv0, ctxa[nt][1] * inv0 };
        float2 o1 = { ctxa[nt][2] * inv1, ctxa[nt][3] * inv1 };
        *(float2*)(out0 + col) = o0;
        *(float2*)(out1 + col) = o1;
    }
}

// ---------------------------------------------------------------------------
extern "C" void kernel_launch(void* const* d_in, const int* in_sizes, int n_in,
                              void* d_out, int out_size)
{
    const float* x  = (const float*)d_in[0];
    const float* Wq = (const float*)d_in[1];
    const float* bq = (const float*)d_in[2];
    const float* Wk = (const float*)d_in[3];
    const float* bk = (const float*)d_in[4];
    const float* Wv = (const float*)d_in[5];
    const float* bv = (const float*)d_in[6];
    const float* Wo = (const float*)d_in[7];
    const float* bo = (const float*)d_in[8];
    float* out = (float*)d_out;

    float *q, *k, *v, *ctx;
    cudaGetSymbolAddress((void**)&q,   g_q);
    cudaGetSymbolAddress((void**)&k,   g_k);
    cudaGetSymbolAddress((void**)&v,   g_v);
    cudaGetSymbolAddress((void**)&ctx, g_ctx);

    const int gemm_smem = SMEM_WORDS * 4;
    cudaFuncSetAttribute(gemm_tc_kernel<0>,
                         cudaFuncAttributeMaxDynamicSharedMemorySize, gemm_smem);
    cudaFuncSetAttribute(gemm_tc_kernel<1>,
                         cudaFuncAttributeMaxDynamicSharedMemorySize, gemm_smem);
    const int att_smem = ATT_SMEM_WORDS * 4;   // 61952 bytes
    cudaFuncSetAttribute(attention_mma_kernel,
                         cudaFuncAttributeMaxDynamicSharedMemorySize, att_smem);

    const float qscale = 0.14433756729740643f;   // 1/sqrt(48)

    dim3 gblk(256);
    dim3 ggrd(DIM / 64, MROWS / 128);   // (12, 32)

    gemm_tc_kernel<1><<<ggrd, gblk, gemm_smem>>>(x, Wq, bq, q, MROWS, DIM, DIM, qscale);
    gemm_tc_kernel<1><<<ggrd, gblk, gemm_smem>>>(x, Wk, bk, k, MROWS, DIM, DIM, 1.0f);
    gemm_tc_kernel<1><<<ggrd, gblk, gemm_smem>>>(x, Wv, bv, v, MROWS, DIM, DIM, 1.0f);

    dim3 agrd(S / 128, HEADS, B);       // (16, 16, 2)
    attention_mma_kernel<<<agrd, 256, att_smem>>>(q, k, v, ctx);

    gemm_tc_kernel<0><<<ggrd, gblk, gemm_smem>>>(ctx, Wo, bo, out, MROWS, DIM, DIM, 1.0f);
}

// round 7
// speedup vs baseline: 1.5562x; 1.0793x over previous
#include <cuda_runtime.h>
#include <math.h>
#include <stdint.h>

#define DIM   768
#define HEADS 16
#define DK    48
#define B     2
#define S     2048
#define MROWS (B * S)          // 4096

// Scratch (static device globals — no runtime allocation)
// g_q/g_k hold tf32 bits in [B,H,S,DK] (g_q pre-scaled by 1/sqrt(dk)).
// g_v holds tf32 bits in [B,H,DK,S]  (dk-major, for non-trans ldmatrix).
__device__ float g_q[B * HEADS * S * DK];
__device__ float g_k[B * HEADS * S * DK];
__device__ float g_v[B * HEADS * S * DK];
__device__ float g_ctx[MROWS * DIM];

// ---------------------------------------------------------------------------
// helpers
// ---------------------------------------------------------------------------
__device__ __forceinline__ uint32_t f2tf32(float f) {
    uint32_t r;
    asm("cvt.rna.tf32.f32 %0, %1;" : "=r"(r) : "f"(f));
    return r;
}

__device__ __forceinline__ void mma_tf32(float c[4],
                                         const uint32_t a[4],
                                         const uint32_t b[2]) {
    asm volatile(
        "mma.sync.aligned.m16n8k8.row.col.f32.tf32.tf32.f32 "
        "{%0,%1,%2,%3}, {%4,%5,%6,%7}, {%8,%9}, {%0,%1,%2,%3};\n"
        : "+f"(c[0]), "+f"(c[1]), "+f"(c[2]), "+f"(c[3])
        : "r"(a[0]), "r"(a[1]), "r"(a[2]), "r"(a[3]),
          "r"(b[0]), "r"(b[1]));
}

__device__ __forceinline__ void ldsm_x4(uint32_t& r0, uint32_t& r1,
                                        uint32_t& r2, uint32_t& r3,
                                        uint32_t saddr) {
    asm volatile(
        "ldmatrix.sync.aligned.m8n8.x4.shared.b16 {%0,%1,%2,%3}, [%4];"
        : "=r"(r0), "=r"(r1), "=r"(r2), "=r"(r3) : "r"(saddr));
}

// ---------------------------------------------------------------------------
// Tensor-core GEMM: out = A[M,K] @ W[N,K]^T + bias[N]   (tf32 in, fp32 accum)
// Block tile 128x64, BK=32, 8 warps as 4x2 (warp tile 32x32).
// Fragment loads via ldmatrix.x4 (APITCH=36 words -> conflict-free phases).
// MODE 0: plain fp32 out [M,N].
// MODE 1: scatter tf32 bits of (acc+bias)*oscale to [B,HEADS,S,DK].
// MODE 2: scatter tf32 bits of (acc+bias)        to [B,HEADS,DK,S].
// ---------------------------------------------------------------------------
#define BK 32
#define APITCH 36
#define A_WORDS (128 * APITCH)
#define B_WORDS (64 * APITCH)
#define SMEM_WORDS (2 * (A_WORDS + B_WORDS))

template <int MODE>
__global__ __launch_bounds__(256)
void gemm_tc_kernel(const float* __restrict__ A,
                    const float* __restrict__ W,
                    const float* __restrict__ bias,
                    float* __restrict__ out,
                    int M, int N, int K, float oscale)
{
    extern __shared__ uint32_t smem[];
    uint32_t* As = smem;
    uint32_t* Bs = smem + 2 * A_WORDS;

    const int tid  = threadIdx.x;
    const int lane = tid & 31;
    const int warp = tid >> 5;
    const int warpM = warp >> 1;
    const int warpN = warp & 1;
    const int g   = lane >> 2;
    const int tig = lane & 3;
    const int mi  = lane >> 3;          // ldmatrix matrix index 0..3
    const int ri  = lane & 7;           // ldmatrix row-in-matrix

    const int bm = blockIdx.y * 128;
    const int bn = blockIdx.x * 64;

    const int lrA = tid >> 1;
    const int lkA = (tid & 1) * 16;
    const int lrB = tid >> 2;
    const int lkB = (tid & 3) * 8;

    const float* Aptr = A + (size_t)(bm + lrA) * K + lkA;
    const float* Wptr = W + (size_t)(bn + lrB) * K + lkB;

    const int arow = warpM * 32;
    const int bcol = warpN * 32;

    // ldmatrix lane base addresses (byte smem addresses)
    const uint32_t as_base = (uint32_t)__cvta_generic_to_shared(As);
    const uint32_t bs_base = (uint32_t)__cvta_generic_to_shared(Bs);
    // A frag: row = arow + mt*16 + (mi&1)*8 + ri, col = kc + (mi>>1)*4
    const uint32_t aaddr0 = as_base +
        (((arow + (mi & 1) * 8 + ri) * APITCH) + (mi >> 1) * 4) * 4;
    // B frag: row = bcol + (p*2 + (mi>>1))*8 + ri, col = kc + (mi&1)*4
    const uint32_t baddr0 = bs_base +
        (((bcol + ((mi >> 1) * 8) + ri) * APITCH) + (mi & 1) * 4) * 4;

    float c[2][4][4];
    #pragma unroll
    for (int mt = 0; mt < 2; mt++)
        #pragma unroll
        for (int nt = 0; nt < 4; nt++)
            #pragma unroll
            for (int i = 0; i < 4; i++) c[mt][nt][i] = 0.0f;

    {
        #pragma unroll
        for (int i = 0; i < 4; i++) {
            float4 v = *(const float4*)(Aptr + i * 4);
            uint4 u = { f2tf32(v.x), f2tf32(v.y), f2tf32(v.z), f2tf32(v.w) };
            *(uint4*)&As[lrA * APITCH + lkA + i * 4] = u;
        }
        #pragma unroll
        for (int i = 0; i < 2; i++) {
            float4 v = *(const float4*)(Wptr + i * 4);
            uint4 u = { f2tf32(v.x), f2tf32(v.y), f2tf32(v.z), f2tf32(v.w) };
            *(uint4*)&Bs[lrB * APITCH + lkB + i * 4] = u;
        }
    }
    __syncthreads();

    int buf = 0;
    for (int k0 = BK; k0 <= K; k0 += BK) {
        float4 pa[4], pw[2];
        const bool more = (k0 < K);
        if (more) {
            #pragma unroll
            for (int i = 0; i < 4; i++) pa[i] = *(const float4*)(Aptr + k0 + i * 4);
            #pragma unroll
            for (int i = 0; i < 2; i++) pw[i] = *(const float4*)(Wptr + k0 + i * 4);
        }

        const uint32_t abuf = aaddr0 + (uint32_t)buf * A_WORDS * 4;
        const uint32_t bbuf = baddr0 + (uint32_t)buf * B_WORDS * 4;
        #pragma unroll
        for (int ks = 0; ks < 4; ks++) {
            const uint32_t koff = ks * 32;           // kc*4 bytes
            uint32_t afr[2][4], bfr[4][2];
            #pragma unroll
            for (int mt = 0; mt < 2; mt++)
                ldsm_x4(afr[mt][0], afr[mt][1], afr[mt][2], afr[mt][3],
                        abuf + mt * (16 * APITCH * 4) + koff);
            #pragma unroll
            for (int p = 0; p < 2; p++)
                ldsm_x4(bfr[2*p][0], bfr[2*p][1], bfr[2*p+1][0], bfr[2*p+1][1],
                        bbuf + p * (16 * APITCH * 4) + koff);
            #pragma unroll
            for (int mt = 0; mt < 2; mt++)
                #pragma unroll
                for (int nt = 0; nt < 4; nt++)
                    mma_tf32(c[mt][nt], afr[mt], bfr[nt]);
        }

        if (more) {
            buf ^= 1;
            uint32_t* Aw = As + buf * A_WORDS;
            uint32_t* Bw = Bs + buf * B_WORDS;
            __syncthreads();
            #pragma unroll
            for (int i = 0; i < 4; i++) {
                uint4 u = { f2tf32(pa[i].x), f2tf32(pa[i].y), f2tf32(pa[i].z), f2tf32(pa[i].w) };
                *(uint4*)&Aw[lrA * APITCH + lkA + i * 4] = u;
            }
            #pragma unroll
            for (int i = 0; i < 2; i++) {
                uint4 u = { f2tf32(pw[i].x), f2tf32(pw[i].y), f2tf32(pw[i].z), f2tf32(pw[i].w) };
                *(uint4*)&Bw[lrB * APITCH + lkB + i * 4] = u;
            }
            __syncthreads();
        }
    }

    #pragma unroll
    for (int mt = 0; mt < 2; mt++) {
        #pragma unroll
        for (int nt = 0; nt < 4; nt++) {
            #pragma unroll
            for (int i = 0; i < 4; i++) {
                const int m = bm + arow + mt * 16 + g + (i >> 1) * 8;
                const int n = bn + bcol + nt * 8 + 2 * tig + (i & 1);
                const float v = c[mt][nt][i] + bias[n];
                if (MODE == 0) {
                    out[(size_t)m * N + n] = v;
                } else {
                    const int bidx = m / S;
                    const int s    = m % S;
                    const int h    = n / DK;
                    const int d    = n % DK;
                    if (MODE == 1) {
                        out[(((size_t)bidx * HEADS + h) * S + s) * DK + d] =
                            __uint_as_float(f2tf32(v * oscale));
                    } else {
                        out[(((size_t)bidx * HEADS + h) * DK + d) * S + s] =
                            __uint_as_float(f2tf32(v));
                    }
                }
            }
        }
    }
}

// ---------------------------------------------------------------------------
// Tensor-core flash attention (tf32 mma + ldmatrix fragment loads).
// Q/K pre-converted tf32 [B,H,S,DK] (Q pre-scaled); V pre-converted tf32
// dk-major [B,H,DK,S]. All mma fragments loaded with ldmatrix.x4.
// ---------------------------------------------------------------------------
#define KPITCH 52          // K tile pitch (words); 13*16B rows -> LDSM clean
#define VTP    68          // V^T tile pitch (words); 17*16B rows
#define PPITCH 68          // P/Q tile pitch (words); 17*16B rows
#define ATT_SMEM_WORDS (64 * KPITCH + 48 * VTP + 128 * PPITCH)

__global__ __launch_bounds__(256)
void attention_mma_kernel(const float* __restrict__ Q,
                          const float* __restrict__ K,
                          const float* __restrict__ V,
                          float* __restrict__ ctx)
{
    extern __shared__ uint32_t sm[];
    uint32_t* Ks = sm;                              // [64][KPITCH]
    uint32_t* Vt = sm + 64 * KPITCH;                // [48][VTP]  (dk-major)
    uint32_t* Ps = sm + 64 * KPITCH + 48 * VTP;     // [128][PPITCH]

    const int qt   = blockIdx.x;
    const int h    = blockIdx.y;
    const int b    = blockIdx.z;
    const int tid  = threadIdx.x;
    const int lane = tid & 31;
    const int warp = tid >> 5;
    const int g    = lane >> 2;
    const int tig  = lane & 3;
    const int mi   = lane >> 3;
    const int ri   = lane & 7;
    const int r0   = warp * 16;

    const size_t head_off = ((size_t)b * HEADS + h) * S * DK;

    // ldmatrix lane base addresses
    const uint32_t ks_sb = (uint32_t)__cvta_generic_to_shared(Ks);
    const uint32_t vt_sb = (uint32_t)__cvta_generic_to_shared(Vt);
    const uint32_t ps_sb = (uint32_t)__cvta_generic_to_shared(Ps);
    // K B-frag: row = (p*2 + (mi>>1))*8 + ri, col = kc + (mi&1)*4
    const uint32_t kaddr = ks_sb + ((((mi >> 1) * 8 + ri) * KPITCH) + (mi & 1) * 4) * 4;
    // P/Q A-frag: row = r0 + (mi&1)*8 + ri, col = kc + (mi>>1)*4
    const uint32_t paddr = ps_sb + (((r0 + (mi & 1) * 8 + ri) * PPITCH) + (mi >> 1) * 4) * 4;
    // Vt B-frag: row = 16p + (mi>>1)*8 + ri, col = kc + (mi&1)*4
    const uint32_t vaddr = vt_sb + ((((mi >> 1) * 8 + ri) * VTP) + (mi & 1) * 4) * 4;

    // ---- stage Q tile (already tf32 + pre-scaled): pure copy ----
    {
        const uint4* qsrc = (const uint4*)(Q + head_off + (size_t)qt * 128 * DK);
        #pragma unroll
        for (int i = tid; i < 128 * 12; i += 256) {
            const int row = i / 12, c4 = (i % 12) * 4;
            *(uint4*)&Ps[row * PPITCH + c4] = qsrc[i];
        }
    }
    __syncthreads();

    // ---- Q fragments -> registers via ldmatrix ----
    uint32_t qf[6][4];
    #pragma unroll
    for (int ks = 0; ks < 6; ks++)
        ldsm_x4(qf[ks][0], qf[ks][1], qf[ks][2], qf[ks][3], paddr + ks * 32);

    float ctxa[6][4];
    #pragma unroll
    for (int nt = 0; nt < 6; nt++)
        #pragma unroll
        for (int i = 0; i < 4; i++) ctxa[nt][i] = 0.0f;
    float mrun0 = -INFINITY, mrun1 = -INFINITY;
    float lrun0 = 0.0f,      lrun1 = 0.0f;

    const uint4* kb = (const uint4*)(K + head_off);
    const uint4* vb = (const uint4*)(V + ((size_t)b * HEADS + h) * DK * S);

    for (int kt = 0; kt < S / 64; kt++) {
        __syncthreads();     // previous iteration done reading Ks/Vt

        // ---- stage K (row-major) and V^T (dk-major) tiles: uint4 copies ----
        {
            const uint4* ksrc = kb + (size_t)kt * 64 * 12;
            #pragma unroll
            for (int i = tid; i < 768; i += 256) {
                const int row = i / 12, c4 = (i % 12) * 4;
                *(uint4*)&Ks[row * KPITCH + c4] = ksrc[i];
            }
            // V^T: 48 rows (dk) x 64 words (keys) = 48*16 uint4
            #pragma unroll
            for (int i = tid; i < 48 * 16; i += 256) {
                const int row = i >> 4, c16 = i & 15;
                *(uint4*)&Vt[row * VTP + c16 * 4] =
                    vb[(size_t)row * (S / 4) + kt * 16 + c16];
            }
        }
        __syncthreads();

        // ---- scores = Q @ K^T on tensor pipe ----
        float sc[8][4];
        #pragma unroll
        for (int nt = 0; nt < 8; nt++)
            #pragma unroll
            for (int i = 0; i < 4; i++) sc[nt][i] = 0.0f;

        #pragma unroll
        for (int ks = 0; ks < 6; ks++) {
            const uint32_t ka = kaddr + ks * 32;
            #pragma unroll
            for (int p = 0; p < 4; p++) {
                uint32_t b0, b1, b2, b3;
                ldsm_x4(b0, b1, b2, b3, ka + p * (16 * KPITCH * 4));
                uint32_t f0[2] = { b0, b1 };
                uint32_t f1[2] = { b2, b3 };
                mma_tf32(sc[2 * p],     qf[ks], f0);
                mma_tf32(sc[2 * p + 1], qf[ks], f1);
            }
        }

        // ---- online softmax (register + shfl; rows warp-local) ----
        float m0 = sc[0][0], m1 = sc[0][2];
        #pragma unroll
        for (int nt = 0; nt < 8; nt++) {
            m0 = fmaxf(m0, fmaxf(sc[nt][0], sc[nt][1]));
            m1 = fmaxf(m1, fmaxf(sc[nt][2], sc[nt][3]));
        }
        m0 = fmaxf(m0, __shfl_xor_sync(0xFFFFFFFF, m0, 1));
        m0 = fmaxf(m0, __shfl_xor_sync(0xFFFFFFFF, m0, 2));
        m1 = fmaxf(m1, __shfl_xor_sync(0xFFFFFFFF, m1, 1));
        m1 = fmaxf(m1, __shfl_xor_sync(0xFFFFFFFF, m1, 2));

        const float mn0 = fmaxf(mrun0, m0);
        const float mn1 = fmaxf(mrun1, m1);
        const float corr0 = __expf(mrun0 - mn0);   // exp(-inf)=0 first time
        const float corr1 = __expf(mrun1 - mn1);
        mrun0 = mn0; mrun1 = mn1;
        lrun0 *= corr0; lrun1 *= corr1;
        #pragma unroll
        for (int nt = 0; nt < 6; nt++) {
            ctxa[nt][0] *= corr0; ctxa[nt][1] *= corr0;
            ctxa[nt][2] *= corr1; ctxa[nt][3] *= corr1;
        }

        // exp + partial row-sums + store P (tf32) into warp-private slab
        #pragma unroll
        for (int nt = 0; nt < 8; nt++) {
            float p0 = __expf(sc[nt][0] - mn0);
            float p1 = __expf(sc[nt][1] - mn0);
            float p2 = __expf(sc[nt][2] - mn1);
            float p3 = __expf(sc[nt][3] - mn1);
            lrun0 += p0 + p1;
            lrun1 += p2 + p3;
            uint2 u01 = { f2tf32(p0), f2tf32(p1) };
            uint2 u23 = { f2tf32(p2), f2tf32(p3) };
            *(uint2*)&Ps[(r0 + g)     * PPITCH + nt * 8 + 2 * tig] = u01;
            *(uint2*)&Ps[(r0 + g + 8) * PPITCH + nt * 8 + 2 * tig] = u23;
        }
        __syncwarp();

        // ---- ctx += P @ V on tensor pipe ----
        #pragma unroll
        for (int ks = 0; ks < 8; ks++) {
            uint32_t afr[4];
            ldsm_x4(afr[0], afr[1], afr[2], afr[3], paddr + ks * 32);
            #pragma unroll
            for (int p = 0; p < 3; p++) {
                uint32_t b0, b1, b2, b3;
                ldsm_x4(b0, b1, b2, b3, vaddr + p * (16 * VTP * 4) + ks * 32);
                uint32_t f0[2] = { b0, b1 };
                uint32_t f1[2] = { b2, b3 };
                mma_tf32(ctxa[2 * p],     afr, f0);
                mma_tf32(ctxa[2 * p + 1], afr, f1);
            }
        }
    }

    // ---- epilogue: finish row sums, normalize, write ctx [B,S,DIM] ----
    lrun0 += __shfl_xor_sync(0xFFFFFFFF, lrun0, 1);
    lrun0 += __shfl_xor_sync(0xFFFFFFFF, lrun0, 2);
    lrun1 += __shfl_xor_sync(0xFFFFFFFF, lrun1, 1);
    lrun1 += __shfl_xor_sync(0xFFFFFFFF, lrun1, 2);
    const float inv0 = 1.0f / lrun0;
    const float inv1 = 1.0f / lrun1;

    const int srow0 = qt * 128 + r0 + g;
    float* out0 = ctx + ((size_t)b * S + srow0)     * DIM + h * DK;
    float* out1 = ctx + ((size_t)b * S + srow0 + 8) * DIM + h * DK;
    #pragma unroll
    for (int nt = 0; nt < 6; nt++) {
        const int col = nt * 8 + 2 * tig;
        float2 o0 = { ctxa[nt][0] * inv0, ctxa[nt][1] * inv0 };
        float2 o1 = { ctxa[nt][2] * inv1, ctxa[nt][3] * inv1 };
        *(float2*)(out0 + col) = o0;
        *(float2*)(out1 + col) = o1;
    }
}

// ---------------------------------------------------------------------------
extern "C" void kernel_launch(void* const* d_in, const int* in_sizes, int n_in,
                              void* d_out, int out_size)
{
    const float* x  = (const float*)d_in[0];
    const float* Wq = (const float*)d_in[1];
    const float* bq = (const float*)d_in[2];
    const float* Wk = (const float*)d_in[3];
    const float* bk = (const float*)d_in[4];
    const float* Wv = (const float*)d_in[5];
    const float* bv = (const float*)d_in[6];
    const float* Wo = (const float*)d_in[7];
    const float* bo = (const float*)d_in[8];
    float* out = (float*)d_out;

    float *q, *k, *v, *ctx;
    cudaGetSymbolAddress((void**)&q,   g_q);
    cudaGetSymbolAddress((void**)&k,   g_k);
    cudaGetSymbolAddress((void**)&v,   g_v);
    cudaGetSymbolAddress((void**)&ctx, g_ctx);

    const int gemm_smem = SMEM_WORDS * 4;
    cudaFuncSetAttribute(gemm_tc_kernel<0>,
                         cudaFuncAttributeMaxDynamicSharedMemorySize, gemm_smem);
    cudaFuncSetAttribute(gemm_tc_kernel<1>,
                         cudaFuncAttributeMaxDynamicSharedMemorySize, gemm_smem);
    cudaFuncSetAttribute(gemm_tc_kernel<2>,
                         cudaFuncAttributeMaxDynamicSharedMemorySize, gemm_smem);
    const int att_smem = ATT_SMEM_WORDS * 4;   // 61184 bytes
    cudaFuncSetAttribute(attention_mma_kernel,
                         cudaFuncAttributeMaxDynamicSharedMemorySize, att_smem);

    const float qscale = 0.14433756729740643f;   // 1/sqrt(48)

    dim3 gblk(256);
    dim3 ggrd(DIM / 64, MROWS / 128);   // (12, 32)

    gemm_tc_kernel<1><<<ggrd, gblk, gemm_smem>>>(x, Wq, bq, q, MROWS, DIM, DIM, qscale);
    gemm_tc_kernel<1><<<ggrd, gblk, gemm_smem>>>(x, Wk, bk, k, MROWS, DIM, DIM, 1.0f);
    gemm_tc_kernel<2><<<ggrd, gblk, gemm_smem>>>(x, Wv, bv, v, MROWS, DIM, DIM, 1.0f);

    dim3 agrd(S / 128, HEADS, B);       // (16, 16, 2)
    attention_mma_kernel<<<agrd, 256, att_smem>>>(q, k, v, ctx);

    gemm_tc_kernel<0><<<ggrd, gblk, gemm_smem>>>(ctx, Wo, bo, out, MROWS, DIM, DIM, 1.0f);
}

// round 8
// speedup vs baseline: 1.5727x; 1.0106x over previous
#include <cuda_runtime.h>
#include <math.h>
#include <stdint.h>

#define DIM   768
#define HEADS 16
#define DK    48
#define B     2
#define S     2048
#define MROWS (B * S)          // 4096

// Scratch (static device globals — no runtime allocation)
// g_q/g_k hold tf32 bits in [B,H,S,DK] (g_q pre-scaled by 1/sqrt(dk)).
// g_v holds tf32 bits in [B,H,DK,S]  (dk-major, for non-trans ldmatrix).
__device__ float g_q[B * HEADS * S * DK];
__device__ float g_k[B * HEADS * S * DK];
__device__ float g_v[B * HEADS * S * DK];
__device__ float g_ctx[MROWS * DIM];

// ---------------------------------------------------------------------------
// helpers
// ---------------------------------------------------------------------------
__device__ __forceinline__ uint32_t f2tf32(float f) {
    uint32_t r;
    asm("cvt.rna.tf32.f32 %0, %1;" : "=r"(r) : "f"(f));
    return r;
}

__device__ __forceinline__ void mma_tf32(float c[4],
                                         const uint32_t a[4],
                                         const uint32_t b[2]) {
    asm volatile(
        "mma.sync.aligned.m16n8k8.row.col.f32.tf32.tf32.f32 "
        "{%0,%1,%2,%3}, {%4,%5,%6,%7}, {%8,%9}, {%0,%1,%2,%3};\n"
        : "+f"(c[0]), "+f"(c[1]), "+f"(c[2]), "+f"(c[3])
        : "r"(a[0]), "r"(a[1]), "r"(a[2]), "r"(a[3]),
          "r"(b[0]), "r"(b[1]));
}

__device__ __forceinline__ void ldsm_x4(uint32_t& r0, uint32_t& r1,
                                        uint32_t& r2, uint32_t& r3,
                                        uint32_t saddr) {
    asm volatile(
        "ldmatrix.sync.aligned.m8n8.x4.shared.b16 {%0,%1,%2,%3}, [%4];"
        : "=r"(r0), "=r"(r1), "=r"(r2), "=r"(r3) : "r"(saddr));
}

__device__ __forceinline__ void cp_async16(uint32_t saddr, const void* gptr) {
    asm volatile("cp.async.cg.shared.global [%0], [%1], 16;"
                 :: "r"(saddr), "l"(gptr));
}
__device__ __forceinline__ void cp_commit() {
    asm volatile("cp.async.commit_group;");
}
template <int N>
__device__ __forceinline__ void cp_wait() {
    asm volatile("cp.async.wait_group %0;" :: "n"(N));
}

// ---------------------------------------------------------------------------
// Tensor-core GEMM (round-7 version, unchanged):
// out = A[M,K] @ W[N,K]^T + bias[N]   (tf32 in, fp32 accum)
// MODE 0: plain fp32 out [M,N].
// MODE 1: scatter tf32 bits of (acc+bias)*oscale to [B,HEADS,S,DK].
// MODE 2: scatter tf32 bits of (acc+bias)        to [B,HEADS,DK,S].
// ---------------------------------------------------------------------------
#define BK 32
#define APITCH 36
#define A_WORDS (128 * APITCH)
#define B_WORDS (64 * APITCH)
#define SMEM_WORDS (2 * (A_WORDS + B_WORDS))

template <int MODE>
__global__ __launch_bounds__(256)
void gemm_tc_kernel(const float* __restrict__ A,
                    const float* __restrict__ W,
                    const float* __restrict__ bias,
                    float* __restrict__ out,
                    int M, int N, int K, float oscale)
{
    extern __shared__ uint32_t smem[];
    uint32_t* As = smem;
    uint32_t* Bs = smem + 2 * A_WORDS;

    const int tid  = threadIdx.x;
    const int lane = tid & 31;
    const int warp = tid >> 5;
    const int warpM = warp >> 1;
    const int warpN = warp & 1;
    const int g   = lane >> 2;
    const int tig = lane & 3;
    const int mi  = lane >> 3;
    const int ri  = lane & 7;

    const int bm = blockIdx.y * 128;
    const int bn = blockIdx.x * 64;

    const int lrA = tid >> 1;
    const int lkA = (tid & 1) * 16;
    const int lrB = tid >> 2;
    const int lkB = (tid & 3) * 8;

    const float* Aptr = A + (size_t)(bm + lrA) * K + lkA;
    const float* Wptr = W + (size_t)(bn + lrB) * K + lkB;

    const int arow = warpM * 32;
    const int bcol = warpN * 32;

    const uint32_t as_base = (uint32_t)__cvta_generic_to_shared(As);
    const uint32_t bs_base = (uint32_t)__cvta_generic_to_shared(Bs);
    const uint32_t aaddr0 = as_base +
        (((arow + (mi & 1) * 8 + ri) * APITCH) + (mi >> 1) * 4) * 4;
    const uint32_t baddr0 = bs_base +
        (((bcol + ((mi >> 1) * 8) + ri) * APITCH) + (mi & 1) * 4) * 4;

    float c[2][4][4];
    #pragma unroll
    for (int mt = 0; mt < 2; mt++)
        #pragma unroll
        for (int nt = 0; nt < 4; nt++)
            #pragma unroll
            for (int i = 0; i < 4; i++) c[mt][nt][i] = 0.0f;

    {
        #pragma unroll
        for (int i = 0; i < 4; i++) {
            float4 v = *(const float4*)(Aptr + i * 4);
            uint4 u = { f2tf32(v.x), f2tf32(v.y), f2tf32(v.z), f2tf32(v.w) };
            *(uint4*)&As[lrA * APITCH + lkA + i * 4] = u;
        }
        #pragma unroll
        for (int i = 0; i < 2; i++) {
            float4 v = *(const float4*)(Wptr + i * 4);
            uint4 u = { f2tf32(v.x), f2tf32(v.y), f2tf32(v.z), f2tf32(v.w) };
            *(uint4*)&Bs[lrB * APITCH + lkB + i * 4] = u;
        }
    }
    __syncthreads();

    int buf = 0;
    for (int k0 = BK; k0 <= K; k0 += BK) {
        float4 pa[4], pw[2];
        const bool more = (k0 < K);
        if (more) {
            #pragma unroll
            for (int i = 0; i < 4; i++) pa[i] = *(const float4*)(Aptr + k0 + i * 4);
            #pragma unroll
            for (int i = 0; i < 2; i++) pw[i] = *(const float4*)(Wptr + k0 + i * 4);
        }

        const uint32_t abuf = aaddr0 + (uint32_t)buf * A_WORDS * 4;
        const uint32_t bbuf = baddr0 + (uint32_t)buf * B_WORDS * 4;
        #pragma unroll
        for (int ks = 0; ks < 4; ks++) {
            const uint32_t koff = ks * 32;
            uint32_t afr[2][4], bfr[4][2];
            #pragma unroll
            for (int mt = 0; mt < 2; mt++)
                ldsm_x4(afr[mt][0], afr[mt][1], afr[mt][2], afr[mt][3],
                        abuf + mt * (16 * APITCH * 4) + koff);
            #pragma unroll
            for (int p = 0; p < 2; p++)
                ldsm_x4(bfr[2*p][0], bfr[2*p][1], bfr[2*p+1][0], bfr[2*p+1][1],
                        bbuf + p * (16 * APITCH * 4) + koff);
            #pragma unroll
            for (int mt = 0; mt < 2; mt++)
                #pragma unroll
                for (int nt = 0; nt < 4; nt++)
                    mma_tf32(c[mt][nt], afr[mt], bfr[nt]);
        }

        if (more) {
            buf ^= 1;
            uint32_t* Aw = As + buf * A_WORDS;
            uint32_t* Bw = Bs + buf * B_WORDS;
            __syncthreads();
            #pragma unroll
            for (int i = 0; i < 4; i++) {
                uint4 u = { f2tf32(pa[i].x), f2tf32(pa[i].y), f2tf32(pa[i].z), f2tf32(pa[i].w) };
                *(uint4*)&Aw[lrA * APITCH + lkA + i * 4] = u;
            }
            #pragma unroll
            for (int i = 0; i < 2; i++) {
                uint4 u = { f2tf32(pw[i].x), f2tf32(pw[i].y), f2tf32(pw[i].z), f2tf32(pw[i].w) };
                *(uint4*)&Bw[lrB * APITCH + lkB + i * 4] = u;
            }
            __syncthreads();
        }
    }

    #pragma unroll
    for (int mt = 0; mt < 2; mt++) {
        #pragma unroll
        for (int nt = 0; nt < 4; nt++) {
            #pragma unroll
            for (int i = 0; i < 4; i++) {
                const int m = bm + arow + mt * 16 + g + (i >> 1) * 8;
                const int n = bn + bcol + nt * 8 + 2 * tig + (i & 1);
                const float v = c[mt][nt][i] + bias[n];
                if (MODE == 0) {
                    out[(size_t)m * N + n] = v;
                } else {
                    const int bidx = m / S;
                    const int s    = m % S;
                    const int h    = n / DK;
                    const int d    = n % DK;
                    if (MODE == 1) {
                        out[(((size_t)bidx * HEADS + h) * S + s) * DK + d] =
                            __uint_as_float(f2tf32(v * oscale));
                    } else {
                        out[(((size_t)bidx * HEADS + h) * DK + d) * S + s] =
                            __uint_as_float(f2tf32(v));
                    }
                }
            }
        }
    }
}

// ---------------------------------------------------------------------------
// Tensor-core flash attention: tf32 mma + ldmatrix + cp.async double-buffered
// K/V staging (gmem->smem copies for tile kt+1 overlap compute of tile kt).
// ---------------------------------------------------------------------------
#define KPITCH 52
#define VTP    68
#define PPITCH 68
#define KWORDS (64 * KPITCH)     // 3328
#define VWORDS (48 * VTP)        // 3264
#define ATT_SMEM_WORDS (2 * KWORDS + 2 * VWORDS + 128 * PPITCH)

__global__ __launch_bounds__(256)
void attention_mma_kernel(const float* __restrict__ Q,
                          const float* __restrict__ K,
                          const float* __restrict__ V,
                          float* __restrict__ ctx)
{
    extern __shared__ uint32_t sm[];
    uint32_t* Ks = sm;                                   // [2][64][KPITCH]
    uint32_t* Vt = sm + 2 * KWORDS;                      // [2][48][VTP]
    uint32_t* Ps = sm + 2 * KWORDS + 2 * VWORDS;         // [128][PPITCH]

    const int qt   = blockIdx.x;
    const int h    = blockIdx.y;
    const int b    = blockIdx.z;
    const int tid  = threadIdx.x;
    const int lane = tid & 31;
    const int warp = tid >> 5;
    const int g    = lane >> 2;
    const int tig  = lane & 3;
    const int mi   = lane >> 3;
    const int ri   = lane & 7;
    const int r0   = warp * 16;

    const size_t head_off = ((size_t)b * HEADS + h) * S * DK;

    const uint32_t ks_sb = (uint32_t)__cvta_generic_to_shared(Ks);
    const uint32_t vt_sb = (uint32_t)__cvta_generic_to_shared(Vt);
    const uint32_t ps_sb = (uint32_t)__cvta_generic_to_shared(Ps);
    const uint32_t kaddr = ks_sb + ((((mi >> 1) * 8 + ri) * KPITCH) + (mi & 1) * 4) * 4;
    const uint32_t paddr = ps_sb + (((r0 + (mi & 1) * 8 + ri) * PPITCH) + (mi >> 1) * 4) * 4;
    const uint32_t vaddr = vt_sb + ((((mi >> 1) * 8 + ri) * VTP) + (mi & 1) * 4) * 4;

    const uint4* kb = (const uint4*)(K + head_off);
    const uint4* vb = (const uint4*)(V + ((size_t)b * HEADS + h) * DK * S);

    // staging indices for this thread (3 K vectors + 3 V vectors per tile)
    const int krow = tid / 12 + ((tid % 12) >= 6 ? 0 : 0);  // not used; see loop

    // ---- async-stage helper (each thread moves 3+3 uint4) ----
    auto stage_tile = [&](int kt, int bufsel) {
        const uint4* ksrc = kb + (size_t)kt * 768;
        #pragma unroll
        for (int i = tid; i < 768; i += 256) {
            const int row = i / 12, c4 = (i % 12) * 4;
            cp_async16(ks_sb + ((uint32_t)bufsel * KWORDS + row * KPITCH + c4) * 4,
                       ksrc + i);
        }
        #pragma unroll
        for (int i = tid; i < 48 * 16; i += 256) {
            const int row = i >> 4, c16 = i & 15;
            cp_async16(vt_sb + ((uint32_t)bufsel * VWORDS + row * VTP + c16 * 4) * 4,
                       vb + (size_t)row * (S / 4) + kt * 16 + c16);
        }
    };

    // ---- kick off tile 0 copies, then stage Q while they fly ----
    stage_tile(0, 0);
    cp_commit();

    {
        const uint4* qsrc = (const uint4*)(Q + head_off + (size_t)qt * 128 * DK);
        #pragma unroll
        for (int i = tid; i < 128 * 12; i += 256) {
            const int row = i / 12, c4 = (i % 12) * 4;
            *(uint4*)&Ps[row * PPITCH + c4] = qsrc[i];
        }
    }
    __syncthreads();

    // ---- Q fragments -> registers via ldmatrix ----
    uint32_t qf[6][4];
    #pragma unroll
    for (int ks = 0; ks < 6; ks++)
        ldsm_x4(qf[ks][0], qf[ks][1], qf[ks][2], qf[ks][3], paddr + ks * 32);

    float ctxa[6][4];
    #pragma unroll
    for (int nt = 0; nt < 6; nt++)
        #pragma unroll
        for (int i = 0; i < 4; i++) ctxa[nt][i] = 0.0f;
    float mrun0 = -INFINITY, mrun1 = -INFINITY;
    float lrun0 = 0.0f,      lrun1 = 0.0f;

    const int NT = S / 64;      // 32 KV tiles
    for (int kt = 0; kt < NT; kt++) {
        const int buf = kt & 1;

        // issue next tile's copies (they overlap this tile's compute)
        if (kt + 1 < NT) {
            stage_tile(kt + 1, buf ^ 1);
            cp_commit();
            cp_wait<1>();        // tile kt resident; kt+1 in flight
        } else {
            cp_wait<0>();
        }
        __syncthreads();

        const uint32_t kbuf = kaddr + (uint32_t)buf * KWORDS * 4;
        const uint32_t vbuf = vaddr + (uint32_t)buf * VWORDS * 4;

        // ---- scores = Q @ K^T on tensor pipe ----
        float sc[8][4];
        #pragma unroll
        for (int nt = 0; nt < 8; nt++)
            #pragma unroll
            for (int i = 0; i < 4; i++) sc[nt][i] = 0.0f;

        #pragma unroll
        for (int ks = 0; ks < 6; ks++) {
            const uint32_t ka = kbuf + ks * 32;
            #pragma unroll
            for (int p = 0; p < 4; p++) {
                uint32_t b0, b1, b2, b3;
                ldsm_x4(b0, b1, b2, b3, ka + p * (16 * KPITCH * 4));
                uint32_t f0[2] = { b0, b1 };
                uint32_t f1[2] = { b2, b3 };
                mma_tf32(sc[2 * p],     qf[ks], f0);
                mma_tf32(sc[2 * p + 1], qf[ks], f1);
            }
        }

        // ---- online softmax (register + shfl; rows warp-local) ----
        float m0 = sc[0][0], m1 = sc[0][2];
        #pragma unroll
        for (int nt = 0; nt < 8; nt++) {
            m0 = fmaxf(m0, fmaxf(sc[nt][0], sc[nt][1]));
            m1 = fmaxf(m1, fmaxf(sc[nt][2], sc[nt][3]));
        }
        m0 = fmaxf(m0, __shfl_xor_sync(0xFFFFFFFF, m0, 1));
        m0 = fmaxf(m0, __shfl_xor_sync(0xFFFFFFFF, m0, 2));
        m1 = fmaxf(m1, __shfl_xor_sync(0xFFFFFFFF, m1, 1));
        m1 = fmaxf(m1, __shfl_xor_sync(0xFFFFFFFF, m1, 2));

        const float mn0 = fmaxf(mrun0, m0);
        const float mn1 = fmaxf(mrun1, m1);
        const float corr0 = __expf(mrun0 - mn0);
        const float corr1 = __expf(mrun1 - mn1);
        mrun0 = mn0; mrun1 = mn1;
        lrun0 *= corr0; lrun1 *= corr1;
        #pragma unroll
        for (int nt = 0; nt < 6; nt++) {
            ctxa[nt][0] *= corr0; ctxa[nt][1] *= corr0;
            ctxa[nt][2] *= corr1; ctxa[nt][3] *= corr1;
        }

        #pragma unroll
        for (int nt = 0; nt < 8; nt++) {
            float p0 = __expf(sc[nt][0] - mn0);
            float p1 = __expf(sc[nt][1] - mn0);
            float p2 = __expf(sc[nt][2] - mn1);
            float p3 = __expf(sc[nt][3] - mn1);
            lrun0 += p0 + p1;
            lrun1 += p2 + p3;
            uint2 u01 = { f2tf32(p0), f2tf32(p1) };
            uint2 u23 = { f2tf32(p2), f2tf32(p3) };
            *(uint2*)&Ps[(r0 + g)     * PPITCH + nt * 8 + 2 * tig] = u01;
            *(uint2*)&Ps[(r0 + g + 8) * PPITCH + nt * 8 + 2 * tig] = u23;
        }
        __syncwarp();

        // ---- ctx += P @ V on tensor pipe ----
        #pragma unroll
        for (int ks = 0; ks < 8; ks++) {
            uint32_t afr[4];
            ldsm_x4(afr[0], afr[1], afr[2], afr[3], paddr + ks * 32);
            #pragma unroll
            for (int p = 0; p < 3; p++) {
                uint32_t b0, b1, b2, b3;
                ldsm_x4(b0, b1, b2, b3, vbuf + p * (16 * VTP * 4) + ks * 32);
                uint32_t f0[2] = { b0, b1 };
                uint32_t f1[2] = { b2, b3 };
                mma_tf32(ctxa[2 * p],     afr, f0);
                mma_tf32(ctxa[2 * p + 1], afr, f1);
            }
        }
        __syncthreads();   // all warps done reading buf before kt+2 overwrites it
    }

    // ---- epilogue: finish row sums, normalize, write ctx [B,S,DIM] ----
    lrun0 += __shfl_xor_sync(0xFFFFFFFF, lrun0, 1);
    lrun0 += __shfl_xor_sync(0xFFFFFFFF, lrun0, 2);
    lrun1 += __shfl_xor_sync(0xFFFFFFFF, lrun1, 1);
    lrun1 += __shfl_xor_sync(0xFFFFFFFF, lrun1, 2);
    const float inv0 = 1.0f / lrun0;
    const float inv1 = 1.0f / lrun1;

    const int srow0 = qt * 128 + r0 + g;
    float* out0 = ctx + ((size_t)b * S + srow0)     * DIM + h * DK;
    float* out1 = ctx + ((size_t)b * S + srow0 + 8) * DIM + h * DK;
    #pragma unroll
    for (int nt = 0; nt < 6; nt++) {
        const int col = nt * 8 + 2 * tig;
        float2 o0 = { ctxa[nt][0] * inv0, ctxa[nt][1] * inv0 };
        float2 o1 = { ctxa[nt][2] * inv1, ctxa[nt][3] * inv1 };
        *(float2*)(out0 + col) = o0;
        *(float2*)(out1 + col) = o1;
    }
}

// ---------------------------------------------------------------------------
extern "C" void kernel_launch(void* const* d_in, const int* in_sizes, int n_in,
                              void* d_out, int out_size)
{
    const float* x  = (const float*)d_in[0];
    const float* Wq = (const float*)d_in[1];
    const float* bq = (const float*)d_in[2];
    const float* Wk = (const float*)d_in[3];
    const float* bk = (const float*)d_in[4];
    const float* Wv = (const float*)d_in[5];
    const float* bv = (const float*)d_in[6];
    const float* Wo = (const float*)d_in[7];
    const float* bo = (const float*)d_in[8];
    float* out = (float*)d_out;

    float *q, *k, *v, *ctx;
    cudaGetSymbolAddress((void**)&q,   g_q);
    cudaGetSymbolAddress((void**)&k,   g_k);
    cudaGetSymbolAddress((void**)&v,   g_v);
    cudaGetSymbolAddress((void**)&ctx, g_ctx);

    const int gemm_smem = SMEM_WORDS * 4;
    cudaFuncSetAttribute(gemm_tc_kernel<0>,
                         cudaFuncAttributeMaxDynamicSharedMemorySize, gemm_smem);
    cudaFuncSetAttribute(gemm_tc_kernel<1>,
                         cudaFuncAttributeMaxDynamicSharedMemorySize, gemm_smem);
    cudaFuncSetAttribute(gemm_tc_kernel<2>,
                         cudaFuncAttributeMaxDynamicSharedMemorySize, gemm_smem);
    const int att_smem = ATT_SMEM_WORDS * 4;   // 87552 bytes
    cudaFuncSetAttribute(attention_mma_kernel,
                         cudaFuncAttributeMaxDynamicSharedMemorySize, att_smem);

    const float qscale = 0.14433756729740643f;   // 1/sqrt(48)

    dim3 gblk(256);
    dim3 ggrd(DIM / 64, MROWS / 128);   // (12, 32)

    gemm_tc_kernel<1><<<ggrd, gblk, gemm_smem>>>(x, Wq, bq, q, MROWS, DIM, DIM, qscale);
    gemm_tc_kernel<1><<<ggrd, gblk, gemm_smem>>>(x, Wk, bk, k, MROWS, DIM, DIM, 1.0f);
    gemm_tc_kernel<2><<<ggrd, gblk, gemm_smem>>>(x, Wv, bv, v, MROWS, DIM, DIM, 1.0f);

    dim3 agrd(S / 128, HEADS, B);       // (16, 16, 2)
    attention_mma_kernel<<<agrd, 256, att_smem>>>(q, k, v, ctx);

    gemm_tc_kernel<0><<<ggrd, gblk, gemm_smem>>>(ctx, Wo, bo, out, MROWS, DIM, DIM, 1.0f);
}

// round 9
// speedup vs baseline: 1.8356x; 1.1672x over previous
#include <cuda_runtime.h>
#include <cuda_fp16.h>
#include <math.h>
#include <stdint.h>

#define DIM   768
#define HEADS 16
#define DK    48
#define B     2
#define S     2048
#define MROWS (B * S)          // 4096

// Scratch (static device globals — no runtime allocation)
// g_q/g_k: tf32 bits in [B,H,S,DK] (g_q pre-scaled by 1/sqrt(dk)).
// g_v: fp16 in [B,H,S,DK] (stored via reinterpret; only half the bytes used).
__device__ float g_q[B * HEADS * S * DK];
__device__ float g_k[B * HEADS * S * DK];
__device__ float g_v[B * HEADS * S * DK];
__device__ float g_ctx[MROWS * DIM];

// ---------------------------------------------------------------------------
// helpers
// ---------------------------------------------------------------------------
__device__ __forceinline__ uint32_t f2tf32(float f) {
    uint32_t r;
    asm("cvt.rna.tf32.f32 %0, %1;" : "=r"(r) : "f"(f));
    return r;
}

__device__ __forceinline__ uint32_t packh2(float lo, float hi) {
    __half2 h = __floats2half2_rn(lo, hi);
    return *reinterpret_cast<uint32_t*>(&h);
}

__device__ __forceinline__ void mma_tf32(float c[4],
                                         const uint32_t a[4],
                                         const uint32_t b[2]) {
    asm volatile(
        "mma.sync.aligned.m16n8k8.row.col.f32.tf32.tf32.f32 "
        "{%0,%1,%2,%3}, {%4,%5,%6,%7}, {%8,%9}, {%0,%1,%2,%3};\n"
        : "+f"(c[0]), "+f"(c[1]), "+f"(c[2]), "+f"(c[3])
        : "r"(a[0]), "r"(a[1]), "r"(a[2]), "r"(a[3]),
          "r"(b[0]), "r"(b[1]));
}

__device__ __forceinline__ void mma_f16(float c[4],
                                        const uint32_t a[4],
                                        const uint32_t b[2]) {
    asm volatile(
        "mma.sync.aligned.m16n8k16.row.col.f32.f16.f16.f32 "
        "{%0,%1,%2,%3}, {%4,%5,%6,%7}, {%8,%9}, {%0,%1,%2,%3};\n"
        : "+f"(c[0]), "+f"(c[1]), "+f"(c[2]), "+f"(c[3])
        : "r"(a[0]), "r"(a[1]), "r"(a[2]), "r"(a[3]),
          "r"(b[0]), "r"(b[1]));
}

__device__ __forceinline__ void ldsm_x4(uint32_t& r0, uint32_t& r1,
                                        uint32_t& r2, uint32_t& r3,
                                        uint32_t saddr) {
    asm volatile(
        "ldmatrix.sync.aligned.m8n8.x4.shared.b16 {%0,%1,%2,%3}, [%4];"
        : "=r"(r0), "=r"(r1), "=r"(r2), "=r"(r3) : "r"(saddr));
}

__device__ __forceinline__ void ldsm_x4_trans(uint32_t& r0, uint32_t& r1,
                                              uint32_t& r2, uint32_t& r3,
                                              uint32_t saddr) {
    asm volatile(
        "ldmatrix.sync.aligned.m8n8.x4.trans.shared.b16 {%0,%1,%2,%3}, [%4];"
        : "=r"(r0), "=r"(r1), "=r"(r2), "=r"(r3) : "r"(saddr));
}

__device__ __forceinline__ void cp_async16(uint32_t saddr, const void* gptr) {
    asm volatile("cp.async.cg.shared.global [%0], [%1], 16;"
                 :: "r"(saddr), "l"(gptr));
}
__device__ __forceinline__ void cp_commit() {
    asm volatile("cp.async.commit_group;");
}
template <int N>
__device__ __forceinline__ void cp_wait() {
    asm volatile("cp.async.wait_group %0;" :: "n"(N));
}

// ---------------------------------------------------------------------------
// Tensor-core GEMM: out = A[M,K] @ W[N,K]^T + bias[N]   (tf32 in, fp32 accum)
// MODE 0: plain fp32 out [M,N].
// MODE 1: scatter tf32 bits of (acc+bias)*oscale to [B,HEADS,S,DK].
// MODE 3: scatter fp16      of (acc+bias)        to [B,HEADS,S,DK].
// ---------------------------------------------------------------------------
#define BK 32
#define APITCH 36
#define A_WORDS (128 * APITCH)
#define B_WORDS (64 * APITCH)
#define SMEM_WORDS (2 * (A_WORDS + B_WORDS))

template <int MODE>
__global__ __launch_bounds__(256)
void gemm_tc_kernel(const float* __restrict__ A,
                    const float* __restrict__ W,
                    const float* __restrict__ bias,
                    float* __restrict__ out,
                    int M, int N, int K, float oscale)
{
    extern __shared__ uint32_t smem[];
    uint32_t* As = smem;
    uint32_t* Bs = smem + 2 * A_WORDS;

    const int tid  = threadIdx.x;
    const int lane = tid & 31;
    const int warp = tid >> 5;
    const int warpM = warp >> 1;
    const int warpN = warp & 1;
    const int g   = lane >> 2;
    const int tig = lane & 3;
    const int mi  = lane >> 3;
    const int ri  = lane & 7;

    const int bm = blockIdx.y * 128;
    const int bn = blockIdx.x * 64;

    const int lrA = tid >> 1;
    const int lkA = (tid & 1) * 16;
    const int lrB = tid >> 2;
    const int lkB = (tid & 3) * 8;

    const float* Aptr = A + (size_t)(bm + lrA) * K + lkA;
    const float* Wptr = W + (size_t)(bn + lrB) * K + lkB;

    const int arow = warpM * 32;
    const int bcol = warpN * 32;

    const uint32_t as_base = (uint32_t)__cvta_generic_to_shared(As);
    const uint32_t bs_base = (uint32_t)__cvta_generic_to_shared(Bs);
    const uint32_t aaddr0 = as_base +
        (((arow + (mi & 1) * 8 + ri) * APITCH) + (mi >> 1) * 4) * 4;
    const uint32_t baddr0 = bs_base +
        (((bcol + ((mi >> 1) * 8) + ri) * APITCH) + (mi & 1) * 4) * 4;

    float c[2][4][4];
    #pragma unroll
    for (int mt = 0; mt < 2; mt++)
        #pragma unroll
        for (int nt = 0; nt < 4; nt++)
            #pragma unroll
            for (int i = 0; i < 4; i++) c[mt][nt][i] = 0.0f;

    {
        #pragma unroll
        for (int i = 0; i < 4; i++) {
            float4 v = *(const float4*)(Aptr + i * 4);
            uint4 u = { f2tf32(v.x), f2tf32(v.y), f2tf32(v.z), f2tf32(v.w) };
            *(uint4*)&As[lrA * APITCH + lkA + i * 4] = u;
        }
        #pragma unroll
        for (int i = 0; i < 2; i++) {
            float4 v = *(const float4*)(Wptr + i * 4);
            uint4 u = { f2tf32(v.x), f2tf32(v.y), f2tf32(v.z), f2tf32(v.w) };
            *(uint4*)&Bs[lrB * APITCH + lkB + i * 4] = u;
        }
    }
    __syncthreads();

    int buf = 0;
    for (int k0 = BK; k0 <= K; k0 += BK) {
        float4 pa[4], pw[2];
        const bool more = (k0 < K);
        if (more) {
            #pragma unroll
            for (int i = 0; i < 4; i++) pa[i] = *(const float4*)(Aptr + k0 + i * 4);
            #pragma unroll
            for (int i = 0; i < 2; i++) pw[i] = *(const float4*)(Wptr + k0 + i * 4);
        }

        const uint32_t abuf = aaddr0 + (uint32_t)buf * A_WORDS * 4;
        const uint32_t bbuf = baddr0 + (uint32_t)buf * B_WORDS * 4;
        #pragma unroll
        for (int ks = 0; ks < 4; ks++) {
            const uint32_t koff = ks * 32;
            uint32_t afr[2][4], bfr[4][2];
            #pragma unroll
            for (int mt = 0; mt < 2; mt++)
                ldsm_x4(afr[mt][0], afr[mt][1], afr[mt][2], afr[mt][3],
                        abuf + mt * (16 * APITCH * 4) + koff);
            #pragma unroll
            for (int p = 0; p < 2; p++)
                ldsm_x4(bfr[2*p][0], bfr[2*p][1], bfr[2*p+1][0], bfr[2*p+1][1],
                        bbuf + p * (16 * APITCH * 4) + koff);
            #pragma unroll
            for (int mt = 0; mt < 2; mt++)
                #pragma unroll
                for (int nt = 0; nt < 4; nt++)
                    mma_tf32(c[mt][nt], afr[mt], bfr[nt]);
        }

        if (more) {
            buf ^= 1;
            uint32_t* Aw = As + buf * A_WORDS;
            uint32_t* Bw = Bs + buf * B_WORDS;
            __syncthreads();
            #pragma unroll
            for (int i = 0; i < 4; i++) {
                uint4 u = { f2tf32(pa[i].x), f2tf32(pa[i].y), f2tf32(pa[i].z), f2tf32(pa[i].w) };
                *(uint4*)&Aw[lrA * APITCH + lkA + i * 4] = u;
            }
            #pragma unroll
            for (int i = 0; i < 2; i++) {
                uint4 u = { f2tf32(pw[i].x), f2tf32(pw[i].y), f2tf32(pw[i].z), f2tf32(pw[i].w) };
                *(uint4*)&Bw[lrB * APITCH + lkB + i * 4] = u;
            }
            __syncthreads();
        }
    }

    #pragma unroll
    for (int mt = 0; mt < 2; mt++) {
        #pragma unroll
        for (int nt = 0; nt < 4; nt++) {
            #pragma unroll
            for (int i = 0; i < 4; i++) {
                const int m = bm + arow + mt * 16 + g + (i >> 1) * 8;
                const int n = bn + bcol + nt * 8 + 2 * tig + (i & 1);
                const float v = c[mt][nt][i] + bias[n];
                if (MODE == 0) {
                    out[(size_t)m * N + n] = v;
                } else {
                    const int bidx = m / S;
                    const int s    = m % S;
                    const int h    = n / DK;
                    const int d    = n % DK;
                    const size_t idx = (((size_t)bidx * HEADS + h) * S + s) * DK + d;
                    if (MODE == 1) {
                        out[idx] = __uint_as_float(f2tf32(v * oscale));
                    } else {   // MODE 3: fp16 V
                        ((__half*)out)[idx] = __float2half_rn(v);
                    }
                }
            }
        }
    }
}

// ---------------------------------------------------------------------------
// Tensor-core flash attention:
//   QK^T  : tf32 mma m16n8k8, K via ldmatrix.x4 (KPITCH=52)
//   P     : exp'd scores packed to half2 IN REGISTERS (fp16 A-fragments,
//           zero smem traffic for P)
//   PV    : fp16 mma m16n8k16, V (fp16, row-major key x dk) via
//           ldmatrix.x4.trans (pitch 56 halfs -> conflict-free)
//   K/V double-buffered with cp.async.
// ---------------------------------------------------------------------------
#define KPITCH 52
#define PPITCH 68
#define VHP    56                      // V tile pitch in halfs (112B = 7 granules)
#define KWORDS (64 * KPITCH)           // 3328 words per K buffer
#define VWORDS (64 * VHP / 2)          // 1792 words per V buffer
#define ATT_SMEM_WORDS (2 * KWORDS + 2 * VWORDS + 128 * PPITCH)

__global__ __launch_bounds__(256)
void attention_mma_kernel(const float* __restrict__ Q,
                          const float* __restrict__ K,
                          const float* __restrict__ Vf,
                          float* __restrict__ ctx)
{
    extern __shared__ uint32_t sm[];
    uint32_t* Ks = sm;                                   // [2][64][KPITCH]
    uint32_t* Vh = sm + 2 * KWORDS;                      // [2][64][VHP halfs]
    uint32_t* Ps = sm + 2 * KWORDS + 2 * VWORDS;         // [128][PPITCH] (Q stage)

    const int qt   = blockIdx.x;
    const int h    = blockIdx.y;
    const int b    = blockIdx.z;
    const int tid  = threadIdx.x;
    const int lane = tid & 31;
    const int warp = tid >> 5;
    const int g    = lane >> 2;
    const int tig  = lane & 3;
    const int mi   = lane >> 3;
    const int ri   = lane & 7;
    const int r0   = warp * 16;

    const size_t head_off = ((size_t)b * HEADS + h) * S * DK;

    const uint32_t ks_sb = (uint32_t)__cvta_generic_to_shared(Ks);
    const uint32_t vh_sb = (uint32_t)__cvta_generic_to_shared(Vh);
    const uint32_t ps_sb = (uint32_t)__cvta_generic_to_shared(Ps);
    // K B-frag (tf32): row = (mi>>1)*8 + ri (plus 16p), col = kc + (mi&1)*4
    const uint32_t kaddr = ks_sb + ((((mi >> 1) * 8 + ri) * KPITCH) + (mi & 1) * 4) * 4;
    // Q A-frag: row = r0 + (mi&1)*8 + ri, col = kc + (mi>>1)*4
    const uint32_t paddr = ps_sb + (((r0 + (mi & 1) * 8 + ri) * PPITCH) + (mi >> 1) * 4) * 4;
    // V B-frag (fp16, trans): key row = (mi&1)*8 + ri (+16ck), dk col = (mi>>1)*8 (+16t)
    const uint32_t vaddr = vh_sb + (((mi & 1) * 8 + ri) * VHP + (mi >> 1) * 8) * 2;

    const uint4* kb = (const uint4*)(K + head_off);
    const __half* vhg = (const __half*)Vf + head_off;   // fp16 V, [key][dk]

    // ---- async-stage helper ----
    auto stage_tile = [&](int kt, int bufsel) {
        const uint4* ksrc = kb + (size_t)kt * 768;
        #pragma unroll
        for (int i = tid; i < 768; i += 256) {
            const int row = i / 12, c4 = (i % 12) * 4;
            cp_async16(ks_sb + ((uint32_t)bufsel * KWORDS + row * KPITCH + c4) * 4,
                       ksrc + i);
        }
        // V: 64 keys x 48 halfs = 384 uint4
        const __half* vsrc = vhg + (size_t)kt * 64 * DK;
        #pragma unroll
        for (int i = tid; i < 384; i += 256) {
            const int row = i / 6, c8 = i % 6;
            cp_async16(vh_sb + (uint32_t)bufsel * VWORDS * 4 +
                           (row * VHP + c8 * 8) * 2,
                       vsrc + row * DK + c8 * 8);
        }
    };

    // ---- kick off tile 0 copies, then stage Q while they fly ----
    stage_tile(0, 0);
    cp_commit();

    {
        const uint4* qsrc = (const uint4*)(Q + head_off + (size_t)qt * 128 * DK);
        #pragma unroll
        for (int i = tid; i < 128 * 12; i += 256) {
            const int row = i / 12, c4 = (i % 12) * 4;
            *(uint4*)&Ps[row * PPITCH + c4] = qsrc[i];
        }
    }
    __syncthreads();

    // ---- Q fragments -> registers via ldmatrix ----
    uint32_t qf[6][4];
    #pragma unroll
    for (int ks = 0; ks < 6; ks++)
        ldsm_x4(qf[ks][0], qf[ks][1], qf[ks][2], qf[ks][3], paddr + ks * 32);

    float ctxa[6][4];
    #pragma unroll
    for (int nt = 0; nt < 6; nt++)
        #pragma unroll
        for (int i = 0; i < 4; i++) ctxa[nt][i] = 0.0f;
    float mrun0 = -INFINITY, mrun1 = -INFINITY;
    float lrun0 = 0.0f,      lrun1 = 0.0f;

    const int NT = S / 64;      // 32 KV tiles
    for (int kt = 0; kt < NT; kt++) {
        const int buf = kt & 1;

        if (kt + 1 < NT) {
            stage_tile(kt + 1, buf ^ 1);
            cp_commit();
            cp_wait<1>();
        } else {
            cp_wait<0>();
        }
        __syncthreads();

        const uint32_t kbuf = kaddr + (uint32_t)buf * KWORDS * 4;
        const uint32_t vbuf = vaddr + (uint32_t)buf * VWORDS * 4;

        // ---- scores = Q @ K^T on tensor pipe (tf32) ----
        float sc[8][4];
        #pragma unroll
        for (int nt = 0; nt < 8; nt++)
            #pragma unroll
            for (int i = 0; i < 4; i++) sc[nt][i] = 0.0f;

        #pragma unroll
        for (int ks = 0; ks < 6; ks++) {
            const uint32_t ka = kbuf + ks * 32;
            #pragma unroll
            for (int p = 0; p < 4; p++) {
                uint32_t b0, b1, b2, b3;
                ldsm_x4(b0, b1, b2, b3, ka + p * (16 * KPITCH * 4));
                uint32_t f0[2] = { b0, b1 };
                uint32_t f1[2] = { b2, b3 };
                mma_tf32(sc[2 * p],     qf[ks], f0);
                mma_tf32(sc[2 * p + 1], qf[ks], f1);
            }
        }

        // ---- online softmax (register + shfl; rows warp-local) ----
        float m0 = sc[0][0], m1 = sc[0][2];
        #pragma unroll
        for (int nt = 0; nt < 8; nt++) {
            m0 = fmaxf(m0, fmaxf(sc[nt][0], sc[nt][1]));
            m1 = fmaxf(m1, fmaxf(sc[nt][2], sc[nt][3]));
        }
        m0 = fmaxf(m0, __shfl_xor_sync(0xFFFFFFFF, m0, 1));
        m0 = fmaxf(m0, __shfl_xor_sync(0xFFFFFFFF, m0, 2));
        m1 = fmaxf(m1, __shfl_xor_sync(0xFFFFFFFF, m1, 1));
        m1 = fmaxf(m1, __shfl_xor_sync(0xFFFFFFFF, m1, 2));

        const float mn0 = fmaxf(mrun0, m0);
        const float mn1 = fmaxf(mrun1, m1);
        const float corr0 = __expf(mrun0 - mn0);
        const float corr1 = __expf(mrun1 - mn1);
        mrun0 = mn0; mrun1 = mn1;
        lrun0 *= corr0; lrun1 *= corr1;
        #pragma unroll
        for (int nt = 0; nt < 6; nt++) {
            ctxa[nt][0] *= corr0; ctxa[nt][1] *= corr0;
            ctxa[nt][2] *= corr1; ctxa[nt][3] *= corr1;
        }

        // exp in registers (P never touches smem)
        #pragma unroll
        for (int nt = 0; nt < 8; nt++) {
            sc[nt][0] = __expf(sc[nt][0] - mn0);
            sc[nt][1] = __expf(sc[nt][1] - mn0);
            sc[nt][2] = __expf(sc[nt][2] - mn1);
            sc[nt][3] = __expf(sc[nt][3] - mn1);
            lrun0 += sc[nt][0] + sc[nt][1];
            lrun1 += sc[nt][2] + sc[nt][3];
        }

        // ---- ctx += P @ V : fp16 mma, A-frags packed from registers ----
        #pragma unroll
        for (int ck = 0; ck < 4; ck++) {
            uint32_t pa[4];
            pa[0] = packh2(sc[2*ck][0],   sc[2*ck][1]);
            pa[1] = packh2(sc[2*ck][2],   sc[2*ck][3]);
            pa[2] = packh2(sc[2*ck+1][0], sc[2*ck+1][1]);
            pa[3] = packh2(sc[2*ck+1][2], sc[2*ck+1][3]);
            const uint32_t vck = vbuf + ck * (16 * VHP * 2);
            #pragma unroll
            for (int t = 0; t < 3; t++) {
                uint32_t b0, b1, b2, b3;
                ldsm_x4_trans(b0, b1, b2, b3, vck + t * 32);
                uint32_t f0[2] = { b0, b1 };
                uint32_t f1[2] = { b2, b3 };
                mma_f16(ctxa[2 * t],     pa, f0);
                mma_f16(ctxa[2 * t + 1], pa, f1);
            }
        }
        __syncthreads();   // all warps done reading buf before kt+2 overwrites it
    }

    // ---- epilogue: finish row sums, normalize, write ctx [B,S,DIM] ----
    lrun0 += __shfl_xor_sync(0xFFFFFFFF, lrun0, 1);
    lrun0 += __shfl_xor_sync(0xFFFFFFFF, lrun0, 2);
    lrun1 += __shfl_xor_sync(0xFFFFFFFF, lrun1, 1);
    lrun1 += __shfl_xor_sync(0xFFFFFFFF, lrun1, 2);
    const float inv0 = 1.0f / lrun0;
    const float inv1 = 1.0f / lrun1;

    const int srow0 = qt * 128 + r0 + g;
    float* out0 = ctx + ((size_t)b * S + srow0)     * DIM + h * DK;
    float* out1 = ctx + ((size_t)b * S + srow0 + 8) * DIM + h * DK;
    #pragma unroll
    for (int nt = 0; nt < 6; nt++) {
        const int col = nt * 8 + 2 * tig;
        float2 o0 = { ctxa[nt][0] * inv0, ctxa[nt][1] * inv0 };
        float2 o1 = { ctxa[nt][2] * inv1, ctxa[nt][3] * inv1 };
        *(float2*)(out0 + col) = o0;
        *(float2*)(out1 + col) = o1;
    }
}

// ---------------------------------------------------------------------------
extern "C" void kernel_launch(void* const* d_in, const int* in_sizes, int n_in,
                              void* d_out, int out_size)
{
    const float* x  = (const float*)d_in[0];
    const float* Wq = (const float*)d_in[1];
    const float* bq = (const float*)d_in[2];
    const float* Wk = (const float*)d_in[3];
    const float* bk = (const float*)d_in[4];
    const float* Wv = (const float*)d_in[5];
    const float* bv = (const float*)d_in[6];
    const float* Wo = (const float*)d_in[7];
    const float* bo = (const float*)d_in[8];
    float* out = (float*)d_out;

    float *q, *k, *v, *ctx;
    cudaGetSymbolAddress((void**)&q,   g_q);
    cudaGetSymbolAddress((void**)&k,   g_k);
    cudaGetSymbolAddress((void**)&v,   g_v);
    cudaGetSymbolAddress((void**)&ctx, g_ctx);

    const int gemm_smem = SMEM_WORDS * 4;
    cudaFuncSetAttribute(gemm_tc_kernel<0>,
                         cudaFuncAttributeMaxDynamicSharedMemorySize, gemm_smem);
    cudaFuncSetAttribute(gemm_tc_kernel<1>,
                         cudaFuncAttributeMaxDynamicSharedMemorySize, gemm_smem);
    cudaFuncSetAttribute(gemm_tc_kernel<3>,
                         cudaFuncAttributeMaxDynamicSharedMemorySize, gemm_smem);
    const int att_smem = ATT_SMEM_WORDS * 4;   // 75776 bytes
    cudaFuncSetAttribute(attention_mma_kernel,
                         cudaFuncAttributeMaxDynamicSharedMemorySize, att_smem);

    const float qscale = 0.14433756729740643f;   // 1/sqrt(48)

    dim3 gblk(256);
    dim3 ggrd(DIM / 64, MROWS / 128);   // (12, 32)

    gemm_tc_kernel<1><<<ggrd, gblk, gemm_smem>>>(x, Wq, bq, q, MROWS, DIM, DIM, qscale);
    gemm_tc_kernel<1><<<ggrd, gblk, gemm_smem>>>(x, Wk, bk, k, MROWS, DIM, DIM, 1.0f);
    gemm_tc_kernel<3><<<ggrd, gblk, gemm_smem>>>(x, Wv, bv, v, MROWS, DIM, DIM, 1.0f);

    dim3 agrd(S / 128, HEADS, B);       // (16, 16, 2)
    attention_mma_kernel<<<agrd, 256, att_smem>>>(q, k, v, ctx);

    gemm_tc_kernel<0><<<ggrd, gblk, gemm_smem>>>(ctx, Wo, bo, out, MROWS, DIM, DIM, 1.0f);
}

// round 10
// speedup vs baseline: 2.0065x; 1.0931x over previous
#include <cuda_runtime.h>
#include <cuda_fp16.h>
#include <math.h>
#include <stdint.h>

#define DIM   768
#define HEADS 16
#define DK    48
#define B     2
#define S     2048
#define MROWS (B * S)          // 4096

// Scratch (static device globals — no runtime allocation)
// g_q/g_k: tf32 bits in [B,H,S,DK] (g_q pre-scaled by 1/sqrt(dk)).
// g_v: fp16 in [B,H,S,DK] (stored via reinterpret; only half the bytes used).
__device__ float g_q[B * HEADS * S * DK];
__device__ float g_k[B * HEADS * S * DK];
__device__ float g_v[B * HEADS * S * DK];
__device__ float g_ctx[MROWS * DIM];

// ---------------------------------------------------------------------------
// helpers
// ---------------------------------------------------------------------------
__device__ __forceinline__ uint32_t f2tf32(float f) {
    uint32_t r;
    asm("cvt.rna.tf32.f32 %0, %1;" : "=r"(r) : "f"(f));
    return r;
}

__device__ __forceinline__ uint32_t packh2(float lo, float hi) {
    __half2 h = __floats2half2_rn(lo, hi);
    return *reinterpret_cast<uint32_t*>(&h);
}

__device__ __forceinline__ void mma_tf32(float c[4],
                                         const uint32_t a[4],
                                         const uint32_t b[2]) {
    asm volatile(
        "mma.sync.aligned.m16n8k8.row.col.f32.tf32.tf32.f32 "
        "{%0,%1,%2,%3}, {%4,%5,%6,%7}, {%8,%9}, {%0,%1,%2,%3};\n"
        : "+f"(c[0]), "+f"(c[1]), "+f"(c[2]), "+f"(c[3])
        : "r"(a[0]), "r"(a[1]), "r"(a[2]), "r"(a[3]),
          "r"(b[0]), "r"(b[1]));
}

__device__ __forceinline__ void mma_f16(float c[4],
                                        const uint32_t a[4],
                                        const uint32_t b[2]) {
    asm volatile(
        "mma.sync.aligned.m16n8k16.row.col.f32.f16.f16.f32 "
        "{%0,%1,%2,%3}, {%4,%5,%6,%7}, {%8,%9}, {%0,%1,%2,%3};\n"
        : "+f"(c[0]), "+f"(c[1]), "+f"(c[2]), "+f"(c[3])
        : "r"(a[0]), "r"(a[1]), "r"(a[2]), "r"(a[3]),
          "r"(b[0]), "r"(b[1]));
}

__device__ __forceinline__ void ldsm_x4(uint32_t& r0, uint32_t& r1,
                                        uint32_t& r2, uint32_t& r3,
                                        uint32_t saddr) {
    asm volatile(
        "ldmatrix.sync.aligned.m8n8.x4.shared.b16 {%0,%1,%2,%3}, [%4];"
        : "=r"(r0), "=r"(r1), "=r"(r2), "=r"(r3) : "r"(saddr));
}

__device__ __forceinline__ void ldsm_x4_trans(uint32_t& r0, uint32_t& r1,
                                              uint32_t& r2, uint32_t& r3,
                                              uint32_t saddr) {
    asm volatile(
        "ldmatrix.sync.aligned.m8n8.x4.trans.shared.b16 {%0,%1,%2,%3}, [%4];"
        : "=r"(r0), "=r"(r1), "=r"(r2), "=r"(r3) : "r"(saddr));
}

__device__ __forceinline__ void cp_async16(uint32_t saddr, const void* gptr) {
    asm volatile("cp.async.cg.shared.global [%0], [%1], 16;"
                 :: "r"(saddr), "l"(gptr));
}
__device__ __forceinline__ void cp_commit() {
    asm volatile("cp.async.commit_group;");
}
template <int N>
__device__ __forceinline__ void cp_wait() {
    asm volatile("cp.async.wait_group %0;" :: "n"(N));
}

// ---------------------------------------------------------------------------
// Pipelined tensor-core GEMM: out = A[M,K] @ W[N,K]^T + bias[N]
// (fp32 staged raw via cp.async; mma.tf32 truncates mantissa — ~rna accuracy)
// Block tile 128x64, BK=32, 8 warps as 4x2 (warp tile 32x32).
// 3-stage cp.async ring, ONE __syncthreads per K-slab.
// FUSED=true : one launch computes Q,K,V projections. blockIdx.x/12 selects
//   segment: 0 -> q (tf32 bits, *qscale), 1 -> k (tf32 bits), 2 -> v (fp16),
//   all scattered to [B,HEADS,S,DK].
// FUSED=false: plain fp32 out [M,N] (output projection).
// ---------------------------------------------------------------------------
#define BK 32
#define APITCH 36
#define A_WORDS (128 * APITCH)
#define B_WORDS (64 * APITCH)
#define NSTAGE 3
#define GEMM_SMEM_WORDS (NSTAGE * (A_WORDS + B_WORDS))   // 20736 words

template <bool FUSED>
__global__ __launch_bounds__(256)
void gemm_pipe_kernel(const float* __restrict__ A,
                      const float* __restrict__ W0, const float* __restrict__ b0,
                      float* __restrict__ o0,
                      const float* __restrict__ W1, const float* __restrict__ b1,
                      float* __restrict__ o1,
                      const float* __restrict__ W2, const float* __restrict__ b2,
                      float* __restrict__ o2,
                      int M, int N, int K, float qscale)
{
    extern __shared__ uint32_t smem[];
    uint32_t* As = smem;                         // [NSTAGE][128][APITCH]
    uint32_t* Bs = smem + NSTAGE * A_WORDS;      // [NSTAGE][64][APITCH]

    const int tid  = threadIdx.x;
    const int lane = tid & 31;
    const int warp = tid >> 5;
    const int warpM = warp >> 1;
    const int warpN = warp & 1;
    const int g   = lane >> 2;
    const int tig = lane & 3;
    const int mi  = lane >> 3;
    const int ri  = lane & 7;

    int seg = 0, bnx = blockIdx.x;
    const float* W = W0; const float* bias = b0; float* out = o0;
    if (FUSED) {
        seg = blockIdx.x / 12;
        bnx = blockIdx.x % 12;
        if (seg == 1)      { W = W1; bias = b1; out = o1; }
        else if (seg == 2) { W = W2; bias = b2; out = o2; }
    }

    const int bm = blockIdx.y * 128;
    const int bn = bnx * 64;

    const int lrA = tid >> 1;                // 0..127
    const int lkA = (tid & 1) * 16;          // 0 / 16
    const int lrB = tid >> 2;                // 0..63
    const int lkB = (tid & 3) * 8;           // 0/8/16/24

    const float* Aptr = A + (size_t)(bm + lrA) * K + lkA;
    const float* Wptr = W + (size_t)(bn + lrB) * K + lkB;

    const int arow = warpM * 32;
    const int bcol = warpN * 32;

    const uint32_t as_sb = (uint32_t)__cvta_generic_to_shared(As);
    const uint32_t bs_sb = (uint32_t)__cvta_generic_to_shared(Bs);
    const uint32_t aaddr0 = as_sb +
        (((arow + (mi & 1) * 8 + ri) * APITCH) + (mi >> 1) * 4) * 4;
    const uint32_t baddr0 = bs_sb +
        (((bcol + ((mi >> 1) * 8) + ri) * APITCH) + (mi & 1) * 4) * 4;

    auto stage = [&](int s, int buf) {
        const float* ap = Aptr + s * BK;
        #pragma unroll
        for (int i = 0; i < 4; i++)
            cp_async16(as_sb + ((uint32_t)buf * A_WORDS + lrA * APITCH + lkA + i * 4) * 4,
                       ap + i * 4);
        const float* wp = Wptr + s * BK;
        #pragma unroll
        for (int i = 0; i < 2; i++)
            cp_async16(bs_sb + ((uint32_t)buf * B_WORDS + lrB * APITCH + lkB + i * 4) * 4,
                       wp + i * 4);
    };

    float c[2][4][4];
    #pragma unroll
    for (int mt = 0; mt < 2; mt++)
        #pragma unroll
        for (int nt = 0; nt < 4; nt++)
            #pragma unroll
            for (int i = 0; i < 4; i++) c[mt][nt][i] = 0.0f;

    const int NS = K / BK;      // 24 slabs
    stage(0, 0); cp_commit();
    stage(1, 1); cp_commit();

    for (int s = 0; s < NS; s++) {
        cp_wait<1>();
        __syncthreads();
        if (s + 2 < NS) { stage(s + 2, (s + 2) % NSTAGE); cp_commit(); }

        const int buf = s % NSTAGE;
        const uint32_t abuf = aaddr0 + (uint32_t)buf * A_WORDS * 4;
        const uint32_t bbuf = baddr0 + (uint32_t)buf * B_WORDS * 4;
        #pragma unroll
        for (int ks = 0; ks < 4; ks++) {
            const uint32_t koff = ks * 32;
            uint32_t afr[2][4], bfr[4][2];
            #pragma unroll
            for (int mt = 0; mt < 2; mt++)
                ldsm_x4(afr[mt][0], afr[mt][1], afr[mt][2], afr[mt][3],
                        abuf + mt * (16 * APITCH * 4) + koff);
            #pragma unroll
            for (int p = 0; p < 2; p++)
                ldsm_x4(bfr[2*p][0], bfr[2*p][1], bfr[2*p+1][0], bfr[2*p+1][1],
                        bbuf + p * (16 * APITCH * 4) + koff);
            #pragma unroll
            for (int mt = 0; mt < 2; mt++)
                #pragma unroll
                for (int nt = 0; nt < 4; nt++)
                    mma_tf32(c[mt][nt], afr[mt], bfr[nt]);
        }
    }

    // ---- epilogue ----
    #pragma unroll
    for (int mt = 0; mt < 2; mt++) {
        #pragma unroll
        for (int nt = 0; nt < 4; nt++) {
            #pragma unroll
            for (int i = 0; i < 4; i++) {
                const int m = bm + arow + mt * 16 + g + (i >> 1) * 8;
                const int n = bn + bcol + nt * 8 + 2 * tig + (i & 1);
                const float v = c[mt][nt][i] + bias[n];
                if (!FUSED) {
                    out[(size_t)m * N + n] = v;
                } else {
                    const int bidx = m / S;
                    const int s_   = m % S;
                    const int h    = n / DK;
                    const int d    = n % DK;
                    const size_t idx = (((size_t)bidx * HEADS + h) * S + s_) * DK + d;
                    if (seg == 0)      out[idx] = __uint_as_float(f2tf32(v * qscale));
                    else if (seg == 1) out[idx] = __uint_as_float(f2tf32(v));
                    else               ((__half*)out)[idx] = __float2half_rn(v);
                }
            }
        }
    }
}

// ---------------------------------------------------------------------------
// Tensor-core flash attention (round-9 version, measured 145us — unchanged):
//   QK^T tf32 mma (K via ldmatrix.x4), P packed to half2 in registers,
//   PV fp16 mma (V via ldmatrix.x4.trans), cp.async double-buffered K/V.
// ---------------------------------------------------------------------------
#define KPITCH 52
#define PPITCH 68
#define VHP    56
#define KWORDS (64 * KPITCH)
#define VWORDS (64 * VHP / 2)
#define ATT_SMEM_WORDS (2 * KWORDS + 2 * VWORDS + 128 * PPITCH)

__global__ __launch_bounds__(256)
void attention_mma_kernel(const float* __restrict__ Q,
                          const float* __restrict__ K,
                          const float* __restrict__ Vf,
                          float* __restrict__ ctx)
{
    extern __shared__ uint32_t sm[];
    uint32_t* Ks = sm;
    uint32_t* Vh = sm + 2 * KWORDS;
    uint32_t* Ps = sm + 2 * KWORDS + 2 * VWORDS;

    const int qt   = blockIdx.x;
    const int h    = blockIdx.y;
    const int b    = blockIdx.z;
    const int tid  = threadIdx.x;
    const int lane = tid & 31;
    const int warp = tid >> 5;
    const int g    = lane >> 2;
    const int tig  = lane & 3;
    const int mi   = lane >> 3;
    const int ri   = lane & 7;
    const int r0   = warp * 16;

    const size_t head_off = ((size_t)b * HEADS + h) * S * DK;

    const uint32_t ks_sb = (uint32_t)__cvta_generic_to_shared(Ks);
    const uint32_t vh_sb = (uint32_t)__cvta_generic_to_shared(Vh);
    const uint32_t ps_sb = (uint32_t)__cvta_generic_to_shared(Ps);
    const uint32_t kaddr = ks_sb + ((((mi >> 1) * 8 + ri) * KPITCH) + (mi & 1) * 4) * 4;
    const uint32_t paddr = ps_sb + (((r0 + (mi & 1) * 8 + ri) * PPITCH) + (mi >> 1) * 4) * 4;
    const uint32_t vaddr = vh_sb + (((mi & 1) * 8 + ri) * VHP + (mi >> 1) * 8) * 2;

    const uint4* kb = (const uint4*)(K + head_off);
    const __half* vhg = (const __half*)Vf + head_off;

    auto stage_tile = [&](int kt, int bufsel) {
        const uint4* ksrc = kb + (size_t)kt * 768;
        #pragma unroll
        for (int i = tid; i < 768; i += 256) {
            const int row = i / 12, c4 = (i % 12) * 4;
            cp_async16(ks_sb + ((uint32_t)bufsel * KWORDS + row * KPITCH + c4) * 4,
                       ksrc + i);
        }
        const __half* vsrc = vhg + (size_t)kt * 64 * DK;
        #pragma unroll
        for (int i = tid; i < 384; i += 256) {
            const int row = i / 6, c8 = i % 6;
            cp_async16(vh_sb + (uint32_t)bufsel * VWORDS * 4 +
                           (row * VHP + c8 * 8) * 2,
                       vsrc + row * DK + c8 * 8);
        }
    };

    stage_tile(0, 0);
    cp_commit();

    {
        const uint4* qsrc = (const uint4*)(Q + head_off + (size_t)qt * 128 * DK);
        #pragma unroll
        for (int i = tid; i < 128 * 12; i += 256) {
            const int row = i / 12, c4 = (i % 12) * 4;
            *(uint4*)&Ps[row * PPITCH + c4] = qsrc[i];
        }
    }
    __syncthreads();

    uint32_t qf[6][4];
    #pragma unroll
    for (int ks = 0; ks < 6; ks++)
        ldsm_x4(qf[ks][0], qf[ks][1], qf[ks][2], qf[ks][3], paddr + ks * 32);

    float ctxa[6][4];
    #pragma unroll
    for (int nt = 0; nt < 6; nt++)
        #pragma unroll
        for (int i = 0; i < 4; i++) ctxa[nt][i] = 0.0f;
    float mrun0 = -INFINITY, mrun1 = -INFINITY;
    float lrun0 = 0.0f,      lrun1 = 0.0f;

    const int NT = S / 64;
    for (int kt = 0; kt < NT; kt++) {
        const int buf = kt & 1;

        if (kt + 1 < NT) {
            stage_tile(kt + 1, buf ^ 1);
            cp_commit();
            cp_wait<1>();
        } else {
            cp_wait<0>();
        }
        __syncthreads();

        const uint32_t kbuf = kaddr + (uint32_t)buf * KWORDS * 4;
        const uint32_t vbuf = vaddr + (uint32_t)buf * VWORDS * 4;

        float sc[8][4];
        #pragma unroll
        for (int nt = 0; nt < 8; nt++)
            #pragma unroll
            for (int i = 0; i < 4; i++) sc[nt][i] = 0.0f;

        #pragma unroll
        for (int ks = 0; ks < 6; ks++) {
            const uint32_t ka = kbuf + ks * 32;
            #pragma unroll
            for (int p = 0; p < 4; p++) {
                uint32_t b0, b1, b2, b3;
                ldsm_x4(b0, b1, b2, b3, ka + p * (16 * KPITCH * 4));
                uint32_t f0[2] = { b0, b1 };
                uint32_t f1[2] = { b2, b3 };
                mma_tf32(sc[2 * p],     qf[ks], f0);
                mma_tf32(sc[2 * p + 1], qf[ks], f1);
            }
        }

        float m0 = sc[0][0], m1 = sc[0][2];
        #pragma unroll
        for (int nt = 0; nt < 8; nt++) {
            m0 = fmaxf(m0, fmaxf(sc[nt][0], sc[nt][1]));
            m1 = fmaxf(m1, fmaxf(sc[nt][2], sc[nt][3]));
        }
        m0 = fmaxf(m0, __shfl_xor_sync(0xFFFFFFFF, m0, 1));
        m0 = fmaxf(m0, __shfl_xor_sync(0xFFFFFFFF, m0, 2));
        m1 = fmaxf(m1, __shfl_xor_sync(0xFFFFFFFF, m1, 1));
        m1 = fmaxf(m1, __shfl_xor_sync(0xFFFFFFFF, m1, 2));

        const float mn0 = fmaxf(mrun0, m0);
        const float mn1 = fmaxf(mrun1, m1);
        const float corr0 = __expf(mrun0 - mn0);
        const float corr1 = __expf(mrun1 - mn1);
        mrun0 = mn0; mrun1 = mn1;
        lrun0 *= corr0; lrun1 *= corr1;
        #pragma unroll
        for (int nt = 0; nt < 6; nt++) {
            ctxa[nt][0] *= corr0; ctxa[nt][1] *= corr0;
            ctxa[nt][2] *= corr1; ctxa[nt][3] *= corr1;
        }

        #pragma unroll
        for (int nt = 0; nt < 8; nt++) {
            sc[nt][0] = __expf(sc[nt][0] - mn0);
            sc[nt][1] = __expf(sc[nt][1] - mn0);
            sc[nt][2] = __expf(sc[nt][2] - mn1);
            sc[nt][3] = __expf(sc[nt][3] - mn1);
            lrun0 += sc[nt][0] + sc[nt][1];
            lrun1 += sc[nt][2] + sc[nt][3];
        }

        #pragma unroll
        for (int ck = 0; ck < 4; ck++) {
            uint32_t pa[4];
            pa[0] = packh2(sc[2*ck][0],   sc[2*ck][1]);
            pa[1] = packh2(sc[2*ck][2],   sc[2*ck][3]);
            pa[2] = packh2(sc[2*ck+1][0], sc[2*ck+1][1]);
            pa[3] = packh2(sc[2*ck+1][2], sc[2*ck+1][3]);
            const uint32_t vck = vbuf + ck * (16 * VHP * 2);
            #pragma unroll
            for (int t = 0; t < 3; t++) {
                uint32_t b0, b1, b2, b3;
                ldsm_x4_trans(b0, b1, b2, b3, vck + t * 32);
                uint32_t f0[2] = { b0, b1 };
                uint32_t f1[2] = { b2, b3 };
                mma_f16(ctxa[2 * t],     pa, f0);
                mma_f16(ctxa[2 * t + 1], pa, f1);
            }
        }
        __syncthreads();
    }

    lrun0 += __shfl_xor_sync(0xFFFFFFFF, lrun0, 1);
    lrun0 += __shfl_xor_sync(0xFFFFFFFF, lrun0, 2);
    lrun1 += __shfl_xor_sync(0xFFFFFFFF, lrun1, 1);
    lrun1 += __shfl_xor_sync(0xFFFFFFFF, lrun1, 2);
    const float inv0 = 1.0f / lrun0;
    const float inv1 = 1.0f / lrun1;

    const int srow0 = qt * 128 + r0 + g;
    float* out0 = ctx + ((size_t)b * S + srow0)     * DIM + h * DK;
    float* out1 = ctx + ((size_t)b * S + srow0 + 8) * DIM + h * DK;
    #pragma unroll
    for (int nt = 0; nt < 6; nt++) {
        const int col = nt * 8 + 2 * tig;
        float2 o0 = { ctxa[nt][0] * inv0, ctxa[nt][1] * inv0 };
        float2 o1 = { ctxa[nt][2] * inv1, ctxa[nt][3] * inv1 };
        *(float2*)(out0 + col) = o0;
        *(float2*)(out1 + col) = o1;
    }
}

// ---------------------------------------------------------------------------
extern "C" void kernel_launch(void* const* d_in, const int* in_sizes, int n_in,
                              void* d_out, int out_size)
{
    const float* x  = (const float*)d_in[0];
    const float* Wq = (const float*)d_in[1];
    const float* bq = (const float*)d_in[2];
    const float* Wk = (const float*)d_in[3];
    const float* bk = (const float*)d_in[4];
    const float* Wv = (const float*)d_in[5];
    const float* bv = (const float*)d_in[6];
    const float* Wo = (const float*)d_in[7];
    const float* bo = (const float*)d_in[8];
    float* out = (float*)d_out;

    float *q, *k, *v, *ctx;
    cudaGetSymbolAddress((void**)&q,   g_q);
    cudaGetSymbolAddress((void**)&k,   g_k);
    cudaGetSymbolAddress((void**)&v,   g_v);
    cudaGetSymbolAddress((void**)&ctx, g_ctx);

    const int gemm_smem = GEMM_SMEM_WORDS * 4;   // 82944 bytes
    cudaFuncSetAttribute(gemm_pipe_kernel<true>,
                         cudaFuncAttributeMaxDynamicSharedMemorySize, gemm_smem);
    cudaFuncSetAttribute(gemm_pipe_kernel<false>,
                         cudaFuncAttributeMaxDynamicSharedMemorySize, gemm_smem);
    const int att_smem = ATT_SMEM_WORDS * 4;     // 75776 bytes
    cudaFuncSetAttribute(attention_mma_kernel,
                         cudaFuncAttributeMaxDynamicSharedMemorySize, att_smem);

    const float qscale = 0.14433756729740643f;   // 1/sqrt(48)

    // Fused Q/K/V projections: one launch, 36x32 = 1152 blocks
    dim3 qkv_grid(36, MROWS / 128);
    gemm_pipe_kernel<true><<<qkv_grid, 256, gemm_smem>>>(
        x, Wq, bq, q, Wk, bk, k, Wv, bv, v, MROWS, DIM, DIM, qscale);

    // Attention
    dim3 agrd(S / 128, HEADS, B);                // (16, 16, 2)
    attention_mma_kernel<<<agrd, 256, att_smem>>>(q, k, v, ctx);

    // Output projection
    dim3 o_grid(DIM / 64, MROWS / 128);          // (12, 32)
    gemm_pipe_kernel<false><<<o_grid, 256, gemm_smem>>>(
        ctx, Wo, bo, out, nullptr, nullptr, nullptr,
        nullptr, nullptr, nullptr, MROWS, DIM, DIM, 1.0f);
}